// round 5
// baseline (speedup 1.0000x reference)
#include <cuda_runtime.h>
#include <cuda_bf16.h>
#include <math.h>
#include <stddef.h>
#include <stdint.h>

// ---------------- problem constants ----------------
#define SEQ      33600
#define DMODEL   256
#define NHEADS   8
#define NLEVELS  3
#define NPOINTS  4
#define LP       (NLEVELS * NPOINTS)        // 12
#define HD       (DMODEL / NHEADS)          // 32
#define NOFF     (NHEADS * LP * 2)          // 192
#define NATT     (NHEADS * LP)              // 96
#define N2       (NOFF + NATT)              // 288
#define KHL      512                         // hi|lo weight width
#define OUT_ELEMS  ((size_t)SEQ * DMODEL)
#define ATTN_ELEMS ((size_t)SEQ * NHEADS * LP)

// ---------------- scratch (device globals) ----------------
__device__ float g_value[SEQ * DMODEL];
__device__ float g_raw  [SEQ * N2];
__device__ float g_samp [SEQ * DMODEL];
__device__ float g_b2   [N2];
__device__ __nv_bfloat16 g_wvb[DMODEL * KHL];
__device__ __nv_bfloat16 g_w2b[N2 * KHL];
__device__ __nv_bfloat16 g_wob[DMODEL * KHL];

// ---------------- helpers ----------------
__device__ __forceinline__ uint32_t pack_bf2(__nv_bfloat16 a, __nv_bfloat16 b) {
    __nv_bfloat162 t = __halves2bfloat162(a, b);
    return *reinterpret_cast<uint32_t*>(&t);
}
__device__ __forceinline__ void split_bf16(float x, __nv_bfloat16& h, __nv_bfloat16& l) {
    h = __float2bfloat16_rn(x);
    l = __float2bfloat16_rn(x - __bfloat162float(h));
}
// 8 floats -> 16B hi + 16B lo
__device__ __forceinline__ void cvt8(float4 a, float4 b, uint4& H, uint4& L) {
    __nv_bfloat16 h[8], l[8];
    split_bf16(a.x, h[0], l[0]); split_bf16(a.y, h[1], l[1]);
    split_bf16(a.z, h[2], l[2]); split_bf16(a.w, h[3], l[3]);
    split_bf16(b.x, h[4], l[4]); split_bf16(b.y, h[5], l[5]);
    split_bf16(b.z, h[6], l[6]); split_bf16(b.w, h[7], l[7]);
    H = make_uint4(pack_bf2(h[0],h[1]), pack_bf2(h[2],h[3]), pack_bf2(h[4],h[5]), pack_bf2(h[6],h[7]));
    L = make_uint4(pack_bf2(l[0],l[1]), pack_bf2(l[2],l[3]), pack_bf2(l[4],l[5]), pack_bf2(l[6],l[7]));
}

// ---------------- weight prep: fp32 -> bf16 hi|lo (Wv, [Ws;Wa], Wo) + b2 ----------------
__global__ __launch_bounds__(256) void prep_kernel(
    const float* __restrict__ Wv, const float* __restrict__ Ws, const float* __restrict__ bs,
    const float* __restrict__ Wa, const float* __restrict__ ba, const float* __restrict__ Wo)
{
    int u = blockIdx.x * 256 + threadIdx.x;     // one unit = 8 floats
    const int TOTAL_ROWS = DMODEL + N2 + DMODEL;  // 800
    if (u < TOTAL_ROWS * 32) {
        int row = u >> 5, uc = u & 31;
        const float* src;
        __nv_bfloat16* dst;
        if (row < DMODEL) { src = Wv + (size_t)row * DMODEL; dst = g_wvb + (size_t)row * KHL; }
        else if (row < DMODEL + N2) {
            int n = row - DMODEL;
            src = (n < NOFF) ? (Ws + (size_t)n * DMODEL) : (Wa + (size_t)(n - NOFF) * DMODEL);
            dst = g_w2b + (size_t)n * KHL;
        } else {
            int n = row - DMODEL - N2;
            src = Wo + (size_t)n * DMODEL; dst = g_wob + (size_t)n * KHL;
        }
        float4 a = *(const float4*)(src + uc * 8);
        float4 b = *(const float4*)(src + uc * 8 + 4);
        uint4 H, L; cvt8(a, b, H, L);
        *(uint4*)(dst + uc * 8)          = H;
        *(uint4*)(dst + DMODEL + uc * 8) = L;
    }
    if (u < N2) g_b2[u] = (u < NOFF) ? bs[u] : ba[u - NOFF];
}

// ---------------- fused GEMM: C[M,N] = (A(+A2)) @ Bw^T + bias ----------------
// A fp32 [M,256] (hi/lo split done inline); Bw bf16 [N,512]=[hi|lo].
// 3-pass compensation: Ah·Bh + Ah·Bl + Al·Bh, fp32 accum.
// CTA 256 thr, tile 128x128, 4 K-chunks of 64; warps 4(m) x 2(n).
struct GemmJob {
    const float* A; const float* A2;
    const __nv_bfloat16* Bw; const float* bias;
    float* C; int N;
};

__global__ __launch_bounds__(256, 1) void gemm_kernel(GemmJob j0, GemmJob j1, int xsplit, int M)
{
    extern __shared__ char smem[];
    __nv_bfloat16* Ah = (__nv_bfloat16*)(smem);
    __nv_bfloat16* Al = (__nv_bfloat16*)(smem + 16384);
    __nv_bfloat16* Bh = (__nv_bfloat16*)(smem + 32768);
    __nv_bfloat16* Bl = (__nv_bfloat16*)(smem + 49152);

    const bool first = ((int)blockIdx.x < xsplit);
    GemmJob j = first ? j0 : j1;
    const int nb = first ? blockIdx.x : (blockIdx.x - xsplit);
    const int blk_m = blockIdx.y * 128, blk_n = nb * 128;

    const int tid = threadIdx.x;
    const int wid = tid >> 5, lane = tid & 31;
    const int warp_m = wid & 3, warp_n = wid >> 2;
    const int t4 = lane >> 3, r8 = lane & 7;

    const uint32_t ah_base = (uint32_t)__cvta_generic_to_shared(Ah);
    const uint32_t al_base = (uint32_t)__cvta_generic_to_shared(Al);
    const uint32_t bh_base = (uint32_t)__cvta_generic_to_shared(Bh);
    const uint32_t bl_base = (uint32_t)__cvta_generic_to_shared(Bl);

    // loader mapping: 1024 16B-chunks per tile / 256 threads = 4 each
    int lrow[4], luc[4];
    uint32_t s_off[4];
    #pragma unroll
    for (int i = 0; i < 4; i++) {
        int u = tid + 256 * i;
        lrow[i] = u >> 3; luc[i] = u & 7;
        s_off[i] = (uint32_t)(lrow[i] * 128 + ((luc[i] ^ (lrow[i] & 7)) << 4));
    }

    float acc[2][8][4];
    #pragma unroll
    for (int a = 0; a < 2; a++)
        #pragma unroll
        for (int b = 0; b < 8; b++)
            #pragma unroll
            for (int c = 0; c < 4; c++) acc[a][b][c] = 0.f;

    float4 pa0[4], pa1[4];
    int4 pbh[4], pbl[4];
    const float4 FZ = make_float4(0.f, 0.f, 0.f, 0.f);
    const int4 IZ = make_int4(0, 0, 0, 0);

    // prefetch chunk 0
    #pragma unroll
    for (int i = 0; i < 4; i++) {
        int gm = blk_m + lrow[i];
        if (gm < M) {
            const float* p = j.A + (size_t)gm * DMODEL + luc[i] * 8;
            pa0[i] = *(const float4*)p;
            pa1[i] = *(const float4*)(p + 4);
            if (j.A2) {
                const float* p2 = j.A2 + (size_t)gm * DMODEL + luc[i] * 8;
                float4 u0 = *(const float4*)p2, u1 = *(const float4*)(p2 + 4);
                pa0[i].x += u0.x; pa0[i].y += u0.y; pa0[i].z += u0.z; pa0[i].w += u0.w;
                pa1[i].x += u1.x; pa1[i].y += u1.y; pa1[i].z += u1.z; pa1[i].w += u1.w;
            }
        } else { pa0[i] = FZ; pa1[i] = FZ; }
        int gn = blk_n + lrow[i];
        if (gn < j.N) {
            const __nv_bfloat16* p = j.Bw + (size_t)gn * KHL + luc[i] * 8;
            pbh[i] = *(const int4*)p;
            pbl[i] = *(const int4*)(p + DMODEL);
        } else { pbh[i] = IZ; pbl[i] = IZ; }
    }

    for (int kb = 0; kb < 4; kb++) {
        // store prefetched tiles (A converted to hi/lo)
        #pragma unroll
        for (int i = 0; i < 4; i++) {
            uint4 H, L; cvt8(pa0[i], pa1[i], H, L);
            *(uint4*)((char*)Ah + s_off[i]) = H;
            *(uint4*)((char*)Al + s_off[i]) = L;
            *(int4*)((char*)Bh + s_off[i]) = pbh[i];
            *(int4*)((char*)Bl + s_off[i]) = pbl[i];
        }
        __syncthreads();

        // prefetch next chunk
        if (kb < 3) {
            int kc = (kb + 1) * 64;
            #pragma unroll
            for (int i = 0; i < 4; i++) {
                int gm = blk_m + lrow[i];
                if (gm < M) {
                    const float* p = j.A + (size_t)gm * DMODEL + kc + luc[i] * 8;
                    pa0[i] = *(const float4*)p;
                    pa1[i] = *(const float4*)(p + 4);
                    if (j.A2) {
                        const float* p2 = j.A2 + (size_t)gm * DMODEL + kc + luc[i] * 8;
                        float4 u0 = *(const float4*)p2, u1 = *(const float4*)(p2 + 4);
                        pa0[i].x += u0.x; pa0[i].y += u0.y; pa0[i].z += u0.z; pa0[i].w += u0.w;
                        pa1[i].x += u1.x; pa1[i].y += u1.y; pa1[i].z += u1.z; pa1[i].w += u1.w;
                    }
                } else { pa0[i] = FZ; pa1[i] = FZ; }
                int gn = blk_n + lrow[i];
                if (gn < j.N) {
                    const __nv_bfloat16* p = j.Bw + (size_t)gn * KHL + kc + luc[i] * 8;
                    pbh[i] = *(const int4*)p;
                    pbl[i] = *(const int4*)(p + DMODEL);
                } else { pbh[i] = IZ; pbl[i] = IZ; }
            }
        }

        // compute: 4 k-steps of 16, three products each
        #pragma unroll
        for (int ks = 0; ks < 4; ks++) {
            uint32_t fah[2][4], fal[2][4];
            #pragma unroll
            for (int mi = 0; mi < 2; mi++) {
                int row = warp_m * 32 + mi * 16 + (t4 & 1) * 8 + r8;
                int kch = ks * 2 + (t4 >> 1);
                uint32_t off = (uint32_t)(row * 128 + ((kch ^ (row & 7)) << 4));
                asm volatile("ldmatrix.sync.aligned.m8n8.x4.shared.b16 {%0,%1,%2,%3}, [%4];"
                             : "=r"(fah[mi][0]), "=r"(fah[mi][1]), "=r"(fah[mi][2]), "=r"(fah[mi][3])
                             : "r"(ah_base + off));
                asm volatile("ldmatrix.sync.aligned.m8n8.x4.shared.b16 {%0,%1,%2,%3}, [%4];"
                             : "=r"(fal[mi][0]), "=r"(fal[mi][1]), "=r"(fal[mi][2]), "=r"(fal[mi][3])
                             : "r"(al_base + off));
            }
            uint32_t fbh[4][4], fbl[4][4];
            #pragma unroll
            for (int jj = 0; jj < 4; jj++) {
                int nrow = warp_n * 64 + jj * 16 + (t4 >> 1) * 8 + r8;
                int kch = ks * 2 + (t4 & 1);
                uint32_t off = (uint32_t)(nrow * 128 + ((kch ^ (nrow & 7)) << 4));
                asm volatile("ldmatrix.sync.aligned.m8n8.x4.shared.b16 {%0,%1,%2,%3}, [%4];"
                             : "=r"(fbh[jj][0]), "=r"(fbh[jj][1]), "=r"(fbh[jj][2]), "=r"(fbh[jj][3])
                             : "r"(bh_base + off));
                asm volatile("ldmatrix.sync.aligned.m8n8.x4.shared.b16 {%0,%1,%2,%3}, [%4];"
                             : "=r"(fbl[jj][0]), "=r"(fbl[jj][1]), "=r"(fbl[jj][2]), "=r"(fbl[jj][3])
                             : "r"(bl_base + off));
            }
            #pragma unroll
            for (int mi = 0; mi < 2; mi++)
                #pragma unroll
                for (int nj = 0; nj < 8; nj++) {
                    uint32_t bh0 = fbh[nj >> 1][(nj & 1) * 2 + 0];
                    uint32_t bh1 = fbh[nj >> 1][(nj & 1) * 2 + 1];
                    uint32_t bl0 = fbl[nj >> 1][(nj & 1) * 2 + 0];
                    uint32_t bl1 = fbl[nj >> 1][(nj & 1) * 2 + 1];
                    asm volatile(
                        "mma.sync.aligned.m16n8k16.row.col.f32.bf16.bf16.f32 "
                        "{%0,%1,%2,%3}, {%4,%5,%6,%7}, {%8,%9}, {%0,%1,%2,%3};"
                        : "+f"(acc[mi][nj][0]), "+f"(acc[mi][nj][1]),
                          "+f"(acc[mi][nj][2]), "+f"(acc[mi][nj][3])
                        : "r"(fah[mi][0]), "r"(fah[mi][1]), "r"(fah[mi][2]), "r"(fah[mi][3]),
                          "r"(bh0), "r"(bh1));
                    asm volatile(
                        "mma.sync.aligned.m16n8k16.row.col.f32.bf16.bf16.f32 "
                        "{%0,%1,%2,%3}, {%4,%5,%6,%7}, {%8,%9}, {%0,%1,%2,%3};"
                        : "+f"(acc[mi][nj][0]), "+f"(acc[mi][nj][1]),
                          "+f"(acc[mi][nj][2]), "+f"(acc[mi][nj][3])
                        : "r"(fah[mi][0]), "r"(fah[mi][1]), "r"(fah[mi][2]), "r"(fah[mi][3]),
                          "r"(bl0), "r"(bl1));
                    asm volatile(
                        "mma.sync.aligned.m16n8k16.row.col.f32.bf16.bf16.f32 "
                        "{%0,%1,%2,%3}, {%4,%5,%6,%7}, {%8,%9}, {%0,%1,%2,%3};"
                        : "+f"(acc[mi][nj][0]), "+f"(acc[mi][nj][1]),
                          "+f"(acc[mi][nj][2]), "+f"(acc[mi][nj][3])
                        : "r"(fal[mi][0]), "r"(fal[mi][1]), "r"(fal[mi][2]), "r"(fal[mi][3]),
                          "r"(bh0), "r"(bh1));
                }
        }
        __syncthreads();
    }

    // epilogue
    const int g = lane >> 2, tg = lane & 3;
    #pragma unroll
    for (int mi = 0; mi < 2; mi++) {
        int row0 = blk_m + warp_m * 32 + mi * 16 + g;
        #pragma unroll
        for (int nj = 0; nj < 8; nj++) {
            int col = blk_n + warp_n * 64 + nj * 8 + tg * 2;
            if (col >= j.N) continue;
            float b0 = __ldg(j.bias + col), b1 = __ldg(j.bias + col + 1);
            if (row0 < M) {
                float2 o = make_float2(acc[mi][nj][0] + b0, acc[mi][nj][1] + b1);
                *(float2*)(j.C + (size_t)row0 * j.N + col) = o;
            }
            if (row0 + 8 < M) {
                float2 o = make_float2(acc[mi][nj][2] + b0, acc[mi][nj][3] + b1);
                *(float2*)(j.C + (size_t)(row0 + 8) * j.N + col) = o;
            }
        }
    }
}

// ---------------- sampling: softmax + bilinear gather + weighted sum ----------------
__global__ __launch_bounds__(256) void sample_kernel(
    const float* __restrict__ value,       // [SEQ, 256]
    const float* __restrict__ raw,         // [SEQ, 288]
    const float* __restrict__ refp,        // [SEQ, 3, 2]
    float* __restrict__ out,               // [SEQ, 256]
    float* __restrict__ attn_out)          // [SEQ, 8, 12] or null
{
    const int q    = blockIdx.x;
    const int tid  = threadIdx.x;
    const int head = tid >> 5;
    const int lane = tid & 31;

    __shared__ __align__(16) int   s_idx[NATT][4];
    __shared__ __align__(16) float s_w  [NATT][4];

    const float* rq = raw + (size_t)q * N2;

    float logit = (lane < LP) ? rq[NOFF + head * LP + lane] : -INFINITY;
    float m = logit;
    #pragma unroll
    for (int o = 16; o; o >>= 1) m = fmaxf(m, __shfl_xor_sync(0xffffffffu, m, o));
    float e = (lane < LP) ? expf(logit - m) : 0.f;
    float s = e;
    #pragma unroll
    for (int o = 16; o; o >>= 1) s += __shfl_xor_sync(0xffffffffu, s, o);
    float a = e / s;

    if (lane < LP) {
        if (attn_out) attn_out[((size_t)q * NHEADS + head) * LP + lane] = a;

        const int l = lane >> 2;
        const int Wi = 160 >> l;
        const int start = (l == 0) ? 0 : ((l == 1) ? 25600 : 32000);
        const float dim = (float)Wi;

        const float ox = rq[(head * LP + lane) * 2 + 0];
        const float oy = rq[(head * LP + lane) * 2 + 1];
        const float rx = refp[((size_t)q * NLEVELS + l) * 2 + 0];
        const float ry = refp[((size_t)q * NLEVELS + l) * 2 + 1];
        const float px = (rx + ox / dim) * dim - 0.5f;
        const float py = (ry + oy / dim) * dim - 0.5f;

        const float x0f = floorf(px), y0f = floorf(py);
        const int   x0  = (int)x0f,   y0  = (int)y0f;
        const float wx1 = px - x0f, wy1 = py - y0f;
        const float wx0 = 1.f - wx1, wy0 = 1.f - wy1;

        const bool xok0 = (x0 >= 0)  && (x0 < Wi);
        const bool xok1 = (x0 >= -1) && (x0 + 1 < Wi);
        const bool yok0 = (y0 >= 0)  && (y0 < Wi);
        const bool yok1 = (y0 >= -1) && (y0 + 1 < Wi);

        const int base = start * DMODEL;
        const int r0 = y0 * Wi + x0;
        const int slot = head * LP + lane;

        s_idx[slot][0] = (xok0 && yok0) ? base + r0 * DMODEL            : 0;
        s_idx[slot][1] = (xok1 && yok0) ? base + (r0 + 1) * DMODEL      : 0;
        s_idx[slot][2] = (xok0 && yok1) ? base + (r0 + Wi) * DMODEL     : 0;
        s_idx[slot][3] = (xok1 && yok1) ? base + (r0 + Wi + 1) * DMODEL : 0;
        s_w[slot][0] = (xok0 && yok0) ? a * wy0 * wx0 : 0.f;
        s_w[slot][1] = (xok1 && yok0) ? a * wy0 * wx1 : 0.f;
        s_w[slot][2] = (xok0 && yok1) ? a * wy1 * wx0 : 0.f;
        s_w[slot][3] = (xok1 && yok1) ? a * wy1 * wx1 : 0.f;
    }
    __syncwarp();

    const float* vb = value + head * HD + lane;
    float acc = 0.f;
    #pragma unroll
    for (int lp = 0; lp < LP; lp++) {
        const int4   I  = *reinterpret_cast<const int4*>(s_idx[head * LP + lp]);
        const float4 W4 = *reinterpret_cast<const float4*>(s_w[head * LP + lp]);
        acc = fmaf(W4.x, __ldg(vb + I.x), acc);
        acc = fmaf(W4.y, __ldg(vb + I.y), acc);
        acc = fmaf(W4.z, __ldg(vb + I.z), acc);
        acc = fmaf(W4.w, __ldg(vb + I.w), acc);
    }

    out[(size_t)q * DMODEL + head * HD + lane] = acc;
}

// ---------------- launch ----------------
extern "C" void kernel_launch(void* const* d_in, const int* in_sizes, int n_in,
                              void* d_out, int out_size)
{
    const float* hidden = (const float*)d_in[0];
    const float* enc    = (const float*)d_in[1];
    const float* pos    = (const float*)d_in[2];
    const float* refp   = (const float*)d_in[3];
    const float* Wv     = (const float*)d_in[4];
    const float* bv     = (const float*)d_in[5];
    const float* Ws     = (const float*)d_in[6];
    const float* bs     = (const float*)d_in[7];
    const float* Wa     = (const float*)d_in[8];
    const float* ba     = (const float*)d_in[9];
    const float* Wo     = (const float*)d_in[10];
    const float* bo     = (const float*)d_in[11];

    float* out = (float*)d_out;
    float* attn_ptr = ((size_t)out_size >= OUT_ELEMS + ATTN_ELEMS) ? (out + OUT_ELEMS) : nullptr;

    float *p_value, *p_raw, *p_samp, *p_b2;
    __nv_bfloat16 *p_wvb, *p_w2b, *p_wob;
    cudaGetSymbolAddress((void**)&p_value, g_value);
    cudaGetSymbolAddress((void**)&p_raw,   g_raw);
    cudaGetSymbolAddress((void**)&p_samp,  g_samp);
    cudaGetSymbolAddress((void**)&p_b2,    g_b2);
    cudaGetSymbolAddress((void**)&p_wvb,   g_wvb);
    cudaGetSymbolAddress((void**)&p_w2b,   g_w2b);
    cudaGetSymbolAddress((void**)&p_wob,   g_wob);

    static bool attr_set = false;
    if (!attr_set) {
        cudaFuncSetAttribute(gemm_kernel, cudaFuncAttributeMaxDynamicSharedMemorySize, 65536);
        attr_set = true;
    }

    // 1) weight prep (Wv/[Ws;Wa]/Wo -> bf16 hi|lo, b2)
    prep_kernel<<<100, 256>>>(Wv, Ws, bs, Wa, ba, Wo);

    const int grid_m = (SEQ + 127) / 128;   // 263

    // 2) fused: value = enc@Wv^T + bv  AND  raw = (hidden+pos)@[Ws;Wa]^T + [bs;ba]
    GemmJob jv = { enc,    nullptr, p_wvb, bv,   p_value, DMODEL };
    GemmJob jr = { hidden, pos,     p_w2b, p_b2, p_raw,   N2     };
    {
        dim3 g(5, grid_m);
        gemm_kernel<<<g, 256, 65536>>>(jv, jr, 2, SEQ);
    }

    // 3) softmax + deformable sampling
    sample_kernel<<<SEQ, 256>>>(p_value, p_raw, refp, p_samp, attn_ptr);

    // 4) output = samp @ Wo^T + bo
    GemmJob jo = { p_samp, nullptr, p_wob, bo, out, DMODEL };
    {
        dim3 g(2, grid_m);
        gemm_kernel<<<g, 256, 65536>>>(jo, jo, 2, SEQ);
    }
}

// round 6
// speedup vs baseline: 1.3515x; 1.3515x over previous
#include <cuda_runtime.h>
#include <cuda_bf16.h>
#include <cuda_fp16.h>
#include <math.h>
#include <stddef.h>
#include <stdint.h>

// ---------------- problem constants ----------------
#define SEQ      33600
#define DMODEL   256
#define NHEADS   8
#define NLEVELS  3
#define NPOINTS  4
#define LP       (NLEVELS * NPOINTS)        // 12
#define HD       (DMODEL / NHEADS)          // 32
#define NOFF     (NHEADS * LP * 2)          // 192
#define NATT     (NHEADS * LP)              // 96
#define N2       (NOFF + NATT)              // 288
#define KHL      512                         // hi|lo width
#define OUT_ELEMS  ((size_t)SEQ * DMODEL)
#define ATTN_ELEMS ((size_t)SEQ * NHEADS * LP)

// ---------------- scratch (device globals) ----------------
__device__ __half g_valueh[SEQ * DMODEL];         // value in fp16 (for sampling)
__device__ float  g_raw  [SEQ * N2];
__device__ float  g_b2   [N2];
__device__ __nv_bfloat16 g_encb [SEQ * KHL];      // enc        hi|lo
__device__ __nv_bfloat16 g_hsb  [SEQ * KHL];      // hidden+pos hi|lo
__device__ __nv_bfloat16 g_sampb[SEQ * KHL];      // sampled    hi|lo
__device__ __nv_bfloat16 g_wvb[DMODEL * KHL];
__device__ __nv_bfloat16 g_w2b[N2 * KHL];
__device__ __nv_bfloat16 g_wob[DMODEL * KHL];

// ---------------- helpers ----------------
__device__ __forceinline__ uint32_t pack_bf2(__nv_bfloat16 a, __nv_bfloat16 b) {
    __nv_bfloat162 t = __halves2bfloat162(a, b);
    return *reinterpret_cast<uint32_t*>(&t);
}
__device__ __forceinline__ void split_bf16(float x, __nv_bfloat16& h, __nv_bfloat16& l) {
    h = __float2bfloat16_rn(x);
    l = __float2bfloat16_rn(x - __bfloat162float(h));
}
__device__ __forceinline__ void cvt8(float4 a, float4 b, uint4& H, uint4& L) {
    __nv_bfloat16 h[8], l[8];
    split_bf16(a.x, h[0], l[0]); split_bf16(a.y, h[1], l[1]);
    split_bf16(a.z, h[2], l[2]); split_bf16(a.w, h[3], l[3]);
    split_bf16(b.x, h[4], l[4]); split_bf16(b.y, h[5], l[5]);
    split_bf16(b.z, h[6], l[6]); split_bf16(b.w, h[7], l[7]);
    H = make_uint4(pack_bf2(h[0],h[1]), pack_bf2(h[2],h[3]), pack_bf2(h[4],h[5]), pack_bf2(h[6],h[7]));
    L = make_uint4(pack_bf2(l[0],l[1]), pack_bf2(l[2],l[3]), pack_bf2(l[4],l[5]), pack_bf2(l[6],l[7]));
}
__device__ __forceinline__ void cp_async16(uint32_t dst, const void* src, bool pred) {
    int sz = pred ? 16 : 0;
    asm volatile("cp.async.cg.shared.global [%0], [%1], 16, %2;"
                 :: "r"(dst), "l"(src), "r"(sz) : "memory");
}

// ---------------- weight prep: fp32 -> bf16 hi|lo + b2 ----------------
__global__ __launch_bounds__(256) void prep_kernel(
    const float* __restrict__ Wv, const float* __restrict__ Ws, const float* __restrict__ bs,
    const float* __restrict__ Wa, const float* __restrict__ ba, const float* __restrict__ Wo)
{
    int u = blockIdx.x * 256 + threadIdx.x;     // one unit = 8 floats
    const int TOTAL_ROWS = DMODEL + N2 + DMODEL;  // 800
    if (u < TOTAL_ROWS * 32) {
        int row = u >> 5, uc = u & 31;
        const float* src;
        __nv_bfloat16* dst;
        if (row < DMODEL) { src = Wv + (size_t)row * DMODEL; dst = g_wvb + (size_t)row * KHL; }
        else if (row < DMODEL + N2) {
            int n = row - DMODEL;
            src = (n < NOFF) ? (Ws + (size_t)n * DMODEL) : (Wa + (size_t)(n - NOFF) * DMODEL);
            dst = g_w2b + (size_t)n * KHL;
        } else {
            int n = row - DMODEL - N2;
            src = Wo + (size_t)n * DMODEL; dst = g_wob + (size_t)n * KHL;
        }
        float4 a = *(const float4*)(src + uc * 8);
        float4 b = *(const float4*)(src + uc * 8 + 4);
        uint4 H, L; cvt8(a, b, H, L);
        *(uint4*)(dst + uc * 8)          = H;
        *(uint4*)(dst + DMODEL + uc * 8) = L;
    }
    if (u < N2) g_b2[u] = (u < NOFF) ? bs[u] : ba[u - NOFF];
}

// ---------------- activation conversion: enc and hidden+pos -> bf16 hi|lo ----------------
__global__ __launch_bounds__(256) void conv_act_kernel(
    const float* __restrict__ enc, const float* __restrict__ hidden, const float* __restrict__ pos)
{
    int u = blockIdx.x * 256 + threadIdx.x;
    const int PER = SEQ * 32;                 // units per tensor (8 floats each)
    if (u >= 2 * PER) return;
    bool second = (u >= PER);
    int v = second ? (u - PER) : u;
    int row = v >> 5, uc = v & 31;
    const float* src = (second ? hidden : enc) + (size_t)row * DMODEL + uc * 8;
    float4 a = *(const float4*)(src);
    float4 b = *(const float4*)(src + 4);
    if (second) {
        const float* p2 = pos + (size_t)row * DMODEL + uc * 8;
        float4 u0 = *(const float4*)p2, u1 = *(const float4*)(p2 + 4);
        a.x += u0.x; a.y += u0.y; a.z += u0.z; a.w += u0.w;
        b.x += u1.x; b.y += u1.y; b.z += u1.z; b.w += u1.w;
    }
    uint4 H, L; cvt8(a, b, H, L);
    __nv_bfloat16* dst = (second ? g_hsb : g_encb) + (size_t)row * KHL;
    *(uint4*)(dst + uc * 8)          = H;
    *(uint4*)(dst + DMODEL + uc * 8) = L;
}

// ---------------- GEMM: C[M,N] = A @ Bw^T + bias (compensated bf16, cp.async) ----------------
// A, Bw: bf16 [rows, 512] = [hi(256)|lo(256)]. 12 K-chunks of 64:
// chunks 0-3 Ah*Bh, 4-7 Ah*Bl, 8-11 Al*Bh. fp32 accum.
// CTA 256 thr, tile 128x128, warps 4(m) x 2(n); 2-stage cp.async double buffer.
struct GemmJob {
    const __nv_bfloat16* A;
    const __nv_bfloat16* Bw;
    const float* bias;
    void* C;
    int N;
    int out_half;   // 1: write __half, 0: write float
};

__global__ __launch_bounds__(256, 2) void gemm_kernel(GemmJob j0, GemmJob j1, int xsplit, int M)
{
    extern __shared__ char smem[];   // 2 x (16KB A + 16KB B) = 64 KB

    const bool first = ((int)blockIdx.x < xsplit);
    GemmJob j = first ? j0 : j1;
    const int nb = first ? blockIdx.x : (blockIdx.x - xsplit);
    const int blk_m = blockIdx.y * 128, blk_n = nb * 128;

    const int tid = threadIdx.x;
    const int wid = tid >> 5, lane = tid & 31;
    const int warp_m = wid & 3, warp_n = wid >> 2;
    const int t4 = lane >> 3, r8 = lane & 7;

    const uint32_t s_base = (uint32_t)__cvta_generic_to_shared(smem);

    // loader mapping: 1024 16B-chunks per tile / 256 threads = 4 each
    int lrow[4], luc[4];
    uint32_t s_off[4];
    bool predA[4], predB[4];
    const __nv_bfloat16* srcA[4];
    const __nv_bfloat16* srcB[4];
    #pragma unroll
    for (int i = 0; i < 4; i++) {
        int u = tid + 256 * i;
        lrow[i] = u >> 3; luc[i] = u & 7;
        s_off[i] = (uint32_t)(lrow[i] * 128 + ((luc[i] ^ (lrow[i] & 7)) << 4));
        int gm = blk_m + lrow[i];
        predA[i] = gm < M;
        srcA[i] = j.A + (size_t)(predA[i] ? gm : 0) * KHL + luc[i] * 8;
        int gn = blk_n + lrow[i];
        predB[i] = gn < j.N;
        srcB[i] = j.Bw + (size_t)(predB[i] ? gn : 0) * KHL + luc[i] * 8;
    }

    float acc[2][8][4];
    #pragma unroll
    for (int a = 0; a < 2; a++)
        #pragma unroll
        for (int b = 0; b < 8; b++)
            #pragma unroll
            for (int c = 0; c < 4; c++) acc[a][b][c] = 0.f;

    auto issue = [&](int c, int buf) {
        int pass = c >> 2, kk = (c & 3) * 64;
        int acol = ((pass == 2) ? DMODEL : 0) + kk;
        int bcol = ((pass == 1) ? DMODEL : 0) + kk;
        uint32_t abase = s_base + buf * 32768;
        uint32_t bbase = abase + 16384;
        #pragma unroll
        for (int i = 0; i < 4; i++) {
            cp_async16(abase + s_off[i], srcA[i] + acol, predA[i]);
            cp_async16(bbase + s_off[i], srcB[i] + bcol, predB[i]);
        }
        asm volatile("cp.async.commit_group;" ::: "memory");
    };

    issue(0, 0);

    for (int c = 0; c < 12; c++) {
        if (c + 1 < 12) {
            issue(c + 1, (c + 1) & 1);
            asm volatile("cp.async.wait_group 1;" ::: "memory");
        } else {
            asm volatile("cp.async.wait_group 0;" ::: "memory");
        }
        __syncthreads();

        const uint32_t abase = s_base + (c & 1) * 32768;
        const uint32_t bbase = abase + 16384;

        #pragma unroll
        for (int ks = 0; ks < 4; ks++) {
            uint32_t af[2][4];
            #pragma unroll
            for (int mi = 0; mi < 2; mi++) {
                int row = warp_m * 32 + mi * 16 + (t4 & 1) * 8 + r8;
                int kch = ks * 2 + (t4 >> 1);
                uint32_t addr = abase + (uint32_t)(row * 128 + ((kch ^ (row & 7)) << 4));
                asm volatile("ldmatrix.sync.aligned.m8n8.x4.shared.b16 {%0,%1,%2,%3}, [%4];"
                             : "=r"(af[mi][0]), "=r"(af[mi][1]), "=r"(af[mi][2]), "=r"(af[mi][3])
                             : "r"(addr));
            }
            uint32_t bf[4][4];
            #pragma unroll
            for (int jj = 0; jj < 4; jj++) {
                int nrow = warp_n * 64 + jj * 16 + (t4 >> 1) * 8 + r8;
                int kch = ks * 2 + (t4 & 1);
                uint32_t addr = bbase + (uint32_t)(nrow * 128 + ((kch ^ (nrow & 7)) << 4));
                asm volatile("ldmatrix.sync.aligned.m8n8.x4.shared.b16 {%0,%1,%2,%3}, [%4];"
                             : "=r"(bf[jj][0]), "=r"(bf[jj][1]), "=r"(bf[jj][2]), "=r"(bf[jj][3])
                             : "r"(addr));
            }
            #pragma unroll
            for (int mi = 0; mi < 2; mi++)
                #pragma unroll
                for (int nj = 0; nj < 8; nj++) {
                    uint32_t b0 = bf[nj >> 1][(nj & 1) * 2 + 0];
                    uint32_t b1 = bf[nj >> 1][(nj & 1) * 2 + 1];
                    asm volatile(
                        "mma.sync.aligned.m16n8k16.row.col.f32.bf16.bf16.f32 "
                        "{%0,%1,%2,%3}, {%4,%5,%6,%7}, {%8,%9}, {%0,%1,%2,%3};"
                        : "+f"(acc[mi][nj][0]), "+f"(acc[mi][nj][1]),
                          "+f"(acc[mi][nj][2]), "+f"(acc[mi][nj][3])
                        : "r"(af[mi][0]), "r"(af[mi][1]), "r"(af[mi][2]), "r"(af[mi][3]),
                          "r"(b0), "r"(b1));
                }
        }
        __syncthreads();
    }

    // epilogue
    const int g = lane >> 2, tg = lane & 3;
    #pragma unroll
    for (int mi = 0; mi < 2; mi++) {
        int row0 = blk_m + warp_m * 32 + mi * 16 + g;
        #pragma unroll
        for (int nj = 0; nj < 8; nj++) {
            int col = blk_n + warp_n * 64 + nj * 8 + tg * 2;
            if (col >= j.N) continue;
            float b0 = __ldg(j.bias + col), b1 = __ldg(j.bias + col + 1);
            if (j.out_half) {
                __half* C = (__half*)j.C;
                if (row0 < M) {
                    __half2 o = __floats2half2_rn(acc[mi][nj][0] + b0, acc[mi][nj][1] + b1);
                    *(__half2*)(C + (size_t)row0 * j.N + col) = o;
                }
                if (row0 + 8 < M) {
                    __half2 o = __floats2half2_rn(acc[mi][nj][2] + b0, acc[mi][nj][3] + b1);
                    *(__half2*)(C + (size_t)(row0 + 8) * j.N + col) = o;
                }
            } else {
                float* C = (float*)j.C;
                if (row0 < M) {
                    float2 o = make_float2(acc[mi][nj][0] + b0, acc[mi][nj][1] + b1);
                    *(float2*)(C + (size_t)row0 * j.N + col) = o;
                }
                if (row0 + 8 < M) {
                    float2 o = make_float2(acc[mi][nj][2] + b0, acc[mi][nj][3] + b1);
                    *(float2*)(C + (size_t)(row0 + 8) * j.N + col) = o;
                }
            }
        }
    }
}

// ---------------- sampling: softmax + bilinear gather + weighted sum ----------------
// value in fp16 (64B per warp tap). Output written as bf16 hi|lo for final GEMM.
__global__ __launch_bounds__(256) void sample_kernel(
    const __half* __restrict__ value,      // [SEQ, 256] fp16
    const float* __restrict__ raw,         // [SEQ, 288]
    const float* __restrict__ refp,        // [SEQ, 3, 2]
    __nv_bfloat16* __restrict__ outb,      // [SEQ, 512] hi|lo
    float* __restrict__ attn_out)          // [SEQ, 8, 12] or null
{
    const int q    = blockIdx.x;
    const int tid  = threadIdx.x;
    const int head = tid >> 5;
    const int lane = tid & 31;

    __shared__ __align__(16) int   s_idx[NATT][4];
    __shared__ __align__(16) float s_w  [NATT][4];

    const float* rq = raw + (size_t)q * N2;

    float logit = (lane < LP) ? rq[NOFF + head * LP + lane] : -INFINITY;
    float m = logit;
    #pragma unroll
    for (int o = 16; o; o >>= 1) m = fmaxf(m, __shfl_xor_sync(0xffffffffu, m, o));
    float e = (lane < LP) ? expf(logit - m) : 0.f;
    float s = e;
    #pragma unroll
    for (int o = 16; o; o >>= 1) s += __shfl_xor_sync(0xffffffffu, s, o);
    float a = e / s;

    if (lane < LP) {
        if (attn_out) attn_out[((size_t)q * NHEADS + head) * LP + lane] = a;

        const int l = lane >> 2;
        const int Wi = 160 >> l;
        const int start = (l == 0) ? 0 : ((l == 1) ? 25600 : 32000);
        const float dim = (float)Wi;

        const float ox = rq[(head * LP + lane) * 2 + 0];
        const float oy = rq[(head * LP + lane) * 2 + 1];
        const float rx = refp[((size_t)q * NLEVELS + l) * 2 + 0];
        const float ry = refp[((size_t)q * NLEVELS + l) * 2 + 1];
        const float px = (rx + ox / dim) * dim - 0.5f;
        const float py = (ry + oy / dim) * dim - 0.5f;

        const float x0f = floorf(px), y0f = floorf(py);
        const int   x0  = (int)x0f,   y0  = (int)y0f;
        const float wx1 = px - x0f, wy1 = py - y0f;
        const float wx0 = 1.f - wx1, wy0 = 1.f - wy1;

        const bool xok0 = (x0 >= 0)  && (x0 < Wi);
        const bool xok1 = (x0 >= -1) && (x0 + 1 < Wi);
        const bool yok0 = (y0 >= 0)  && (y0 < Wi);
        const bool yok1 = (y0 >= -1) && (y0 + 1 < Wi);

        const int base = start * DMODEL;
        const int r0 = y0 * Wi + x0;
        const int slot = head * LP + lane;

        s_idx[slot][0] = (xok0 && yok0) ? base + r0 * DMODEL            : 0;
        s_idx[slot][1] = (xok1 && yok0) ? base + (r0 + 1) * DMODEL      : 0;
        s_idx[slot][2] = (xok0 && yok1) ? base + (r0 + Wi) * DMODEL     : 0;
        s_idx[slot][3] = (xok1 && yok1) ? base + (r0 + Wi + 1) * DMODEL : 0;
        s_w[slot][0] = (xok0 && yok0) ? a * wy0 * wx0 : 0.f;
        s_w[slot][1] = (xok1 && yok0) ? a * wy0 * wx1 : 0.f;
        s_w[slot][2] = (xok0 && yok1) ? a * wy1 * wx0 : 0.f;
        s_w[slot][3] = (xok1 && yok1) ? a * wy1 * wx1 : 0.f;
    }
    __syncwarp();

    const __half* vb = value + head * HD + lane;
    float acc = 0.f;
    #pragma unroll
    for (int lp = 0; lp < LP; lp++) {
        const int4   I  = *reinterpret_cast<const int4*>(s_idx[head * LP + lp]);
        const float4 W4 = *reinterpret_cast<const float4*>(s_w[head * LP + lp]);
        acc = fmaf(W4.x, __half2float(__ldg(vb + I.x)), acc);
        acc = fmaf(W4.y, __half2float(__ldg(vb + I.y)), acc);
        acc = fmaf(W4.z, __half2float(__ldg(vb + I.z)), acc);
        acc = fmaf(W4.w, __half2float(__ldg(vb + I.w)), acc);
    }

    __nv_bfloat16 hi, lo;
    split_bf16(acc, hi, lo);
    outb[(size_t)q * KHL + head * HD + lane]          = hi;
    outb[(size_t)q * KHL + DMODEL + head * HD + lane] = lo;
}

// ---------------- launch ----------------
extern "C" void kernel_launch(void* const* d_in, const int* in_sizes, int n_in,
                              void* d_out, int out_size)
{
    const float* hidden = (const float*)d_in[0];
    const float* enc    = (const float*)d_in[1];
    const float* pos    = (const float*)d_in[2];
    const float* refp   = (const float*)d_in[3];
    const float* Wv     = (const float*)d_in[4];
    const float* bv     = (const float*)d_in[5];
    const float* Ws     = (const float*)d_in[6];
    const float* bs     = (const float*)d_in[7];
    const float* Wa     = (const float*)d_in[8];
    const float* ba     = (const float*)d_in[9];
    const float* Wo     = (const float*)d_in[10];
    const float* bo     = (const float*)d_in[11];

    float* out = (float*)d_out;
    float* attn_ptr = ((size_t)out_size >= OUT_ELEMS + ATTN_ELEMS) ? (out + OUT_ELEMS) : nullptr;

    __half* p_valueh; float *p_raw, *p_b2;
    __nv_bfloat16 *p_encb, *p_hsb, *p_sampb, *p_wvb, *p_w2b, *p_wob;
    cudaGetSymbolAddress((void**)&p_valueh, g_valueh);
    cudaGetSymbolAddress((void**)&p_raw,    g_raw);
    cudaGetSymbolAddress((void**)&p_b2,     g_b2);
    cudaGetSymbolAddress((void**)&p_encb,   g_encb);
    cudaGetSymbolAddress((void**)&p_hsb,    g_hsb);
    cudaGetSymbolAddress((void**)&p_sampb,  g_sampb);
    cudaGetSymbolAddress((void**)&p_wvb,    g_wvb);
    cudaGetSymbolAddress((void**)&p_w2b,    g_w2b);
    cudaGetSymbolAddress((void**)&p_wob,    g_wob);

    static bool attr_set = false;
    if (!attr_set) {
        cudaFuncSetAttribute(gemm_kernel, cudaFuncAttributeMaxDynamicSharedMemorySize, 65536);
        attr_set = true;
    }

    // 1) weight prep + activation conversion
    prep_kernel<<<100, 256>>>(Wv, Ws, bs, Wa, ba, Wo);
    conv_act_kernel<<<(2 * SEQ * 32 + 255) / 256, 256>>>(enc, hidden, pos);

    const int grid_m = (SEQ + 127) / 128;   // 263

    // 2) fused: value(fp16) = enc@Wv^T + bv  AND  raw = (hidden+pos)@[Ws;Wa]^T + [bs;ba]
    GemmJob jv = { p_encb, p_wvb, bv,   p_valueh, DMODEL, 1 };
    GemmJob jr = { p_hsb,  p_w2b, p_b2, p_raw,    N2,     0 };
    {
        dim3 g(5, grid_m);
        gemm_kernel<<<g, 256, 65536>>>(jv, jr, 2, SEQ);
    }

    // 3) softmax + deformable sampling (emits bf16 hi|lo)
    sample_kernel<<<SEQ, 256>>>(p_valueh, p_raw, refp, p_sampb, attn_ptr);

    // 4) output = samp @ Wo^T + bo
    GemmJob jo = { p_sampb, p_wob, bo, out, DMODEL, 0 };
    {
        dim3 g(2, grid_m);
        gemm_kernel<<<g, 256, 65536>>>(jo, jo, 2, SEQ);
    }
}

// round 7
// speedup vs baseline: 1.4933x; 1.1049x over previous
#include <cuda_runtime.h>
#include <cuda_bf16.h>
#include <cuda_fp16.h>
#include <math.h>
#include <stddef.h>
#include <stdint.h>

// ---------------- problem constants ----------------
#define SEQ      33600
#define DMODEL   256
#define NHEADS   8
#define NLEVELS  3
#define NPOINTS  4
#define LP       (NLEVELS * NPOINTS)        // 12
#define HD       (DMODEL / NHEADS)          // 32
#define NOFF     (NHEADS * LP * 2)          // 192
#define NATT     (NHEADS * LP)              // 96
#define N2       (NOFF + NATT)              // 288
#define KHL      512                         // hi|lo width
#define OUT_ELEMS  ((size_t)SEQ * DMODEL)
#define ATTN_ELEMS ((size_t)SEQ * NHEADS * LP)

// ---------------- scratch (device globals) ----------------
__device__ __half g_valueh[SEQ * DMODEL];         // value in fp16 (for sampling)
__device__ float  g_raw  [SEQ * N2];
__device__ float  g_b2   [N2];
__device__ __nv_bfloat16 g_encb [SEQ * KHL];      // enc        hi|lo
__device__ __nv_bfloat16 g_hsb  [SEQ * KHL];      // hidden+pos hi|lo
__device__ __nv_bfloat16 g_sampb[SEQ * KHL];      // sampled    hi|lo
__device__ __nv_bfloat16 g_wvb[DMODEL * KHL];
__device__ __nv_bfloat16 g_w2b[N2 * KHL];
__device__ __nv_bfloat16 g_wob[DMODEL * KHL];

// ---------------- helpers ----------------
__device__ __forceinline__ uint32_t pack_bf2(__nv_bfloat16 a, __nv_bfloat16 b) {
    __nv_bfloat162 t = __halves2bfloat162(a, b);
    return *reinterpret_cast<uint32_t*>(&t);
}
__device__ __forceinline__ void split_bf16(float x, __nv_bfloat16& h, __nv_bfloat16& l) {
    h = __float2bfloat16_rn(x);
    l = __float2bfloat16_rn(x - __bfloat162float(h));
}
__device__ __forceinline__ void cvt8(float4 a, float4 b, uint4& H, uint4& L) {
    __nv_bfloat16 h[8], l[8];
    split_bf16(a.x, h[0], l[0]); split_bf16(a.y, h[1], l[1]);
    split_bf16(a.z, h[2], l[2]); split_bf16(a.w, h[3], l[3]);
    split_bf16(b.x, h[4], l[4]); split_bf16(b.y, h[5], l[5]);
    split_bf16(b.z, h[6], l[6]); split_bf16(b.w, h[7], l[7]);
    H = make_uint4(pack_bf2(h[0],h[1]), pack_bf2(h[2],h[3]), pack_bf2(h[4],h[5]), pack_bf2(h[6],h[7]));
    L = make_uint4(pack_bf2(l[0],l[1]), pack_bf2(l[2],l[3]), pack_bf2(l[4],l[5]), pack_bf2(l[6],l[7]));
}
__device__ __forceinline__ void cp_async16(uint32_t dst, const void* src, bool pred) {
    int sz = pred ? 16 : 0;
    asm volatile("cp.async.cg.shared.global [%0], [%1], 16, %2;"
                 :: "r"(dst), "l"(src), "r"(sz) : "memory");
}

// ---------------- weight prep: fp32 -> bf16 hi|lo + b2 ----------------
__global__ __launch_bounds__(256) void prep_kernel(
    const float* __restrict__ Wv, const float* __restrict__ Ws, const float* __restrict__ bs,
    const float* __restrict__ Wa, const float* __restrict__ ba, const float* __restrict__ Wo)
{
    int u = blockIdx.x * 256 + threadIdx.x;     // one unit = 8 floats
    const int TOTAL_ROWS = DMODEL + N2 + DMODEL;  // 800
    if (u < TOTAL_ROWS * 32) {
        int row = u >> 5, uc = u & 31;
        const float* src;
        __nv_bfloat16* dst;
        if (row < DMODEL) { src = Wv + (size_t)row * DMODEL; dst = g_wvb + (size_t)row * KHL; }
        else if (row < DMODEL + N2) {
            int n = row - DMODEL;
            src = (n < NOFF) ? (Ws + (size_t)n * DMODEL) : (Wa + (size_t)(n - NOFF) * DMODEL);
            dst = g_w2b + (size_t)n * KHL;
        } else {
            int n = row - DMODEL - N2;
            src = Wo + (size_t)n * DMODEL; dst = g_wob + (size_t)n * KHL;
        }
        float4 a = *(const float4*)(src + uc * 8);
        float4 b = *(const float4*)(src + uc * 8 + 4);
        uint4 H, L; cvt8(a, b, H, L);
        *(uint4*)(dst + uc * 8)          = H;
        *(uint4*)(dst + DMODEL + uc * 8) = L;
    }
    if (u < N2) g_b2[u] = (u < NOFF) ? bs[u] : ba[u - NOFF];
}

// ---------------- activation conversion: enc and hidden+pos -> bf16 hi|lo ----------------
__global__ __launch_bounds__(256) void conv_act_kernel(
    const float* __restrict__ enc, const float* __restrict__ hidden, const float* __restrict__ pos)
{
    int u = blockIdx.x * 256 + threadIdx.x;
    const int PER = SEQ * 32;                 // units per tensor (8 floats each)
    if (u >= 2 * PER) return;
    bool second = (u >= PER);
    int v = second ? (u - PER) : u;
    int row = v >> 5, uc = v & 31;
    const float* src = (second ? hidden : enc) + (size_t)row * DMODEL + uc * 8;
    float4 a = *(const float4*)(src);
    float4 b = *(const float4*)(src + 4);
    if (second) {
        const float* p2 = pos + (size_t)row * DMODEL + uc * 8;
        float4 u0 = *(const float4*)p2, u1 = *(const float4*)(p2 + 4);
        a.x += u0.x; a.y += u0.y; a.z += u0.z; a.w += u0.w;
        b.x += u1.x; b.y += u1.y; b.z += u1.z; b.w += u1.w;
    }
    uint4 H, L; cvt8(a, b, H, L);
    __nv_bfloat16* dst = (second ? g_hsb : g_encb) + (size_t)row * KHL;
    *(uint4*)(dst + uc * 8)          = H;
    *(uint4*)(dst + DMODEL + uc * 8) = L;
}

// ---------------- GEMM: C[M,N] = A @ Bw^T + bias (compensated bf16, cp.async) ----------------
struct GemmJob {
    const __nv_bfloat16* A;
    const __nv_bfloat16* Bw;
    const float* bias;
    void* C;
    int N;
    int out_half;   // 1: write __half, 0: write float
};

__global__ __launch_bounds__(256, 2) void gemm_kernel(GemmJob j0, GemmJob j1, int xsplit, int M)
{
    extern __shared__ char smem[];   // 2 x (16KB A + 16KB B) = 64 KB

    const bool first = ((int)blockIdx.x < xsplit);
    GemmJob j = first ? j0 : j1;
    const int nb = first ? blockIdx.x : (blockIdx.x - xsplit);
    const int blk_m = blockIdx.y * 128, blk_n = nb * 128;

    const int tid = threadIdx.x;
    const int wid = tid >> 5, lane = tid & 31;
    const int warp_m = wid & 3, warp_n = wid >> 2;
    const int t4 = lane >> 3, r8 = lane & 7;

    const uint32_t s_base = (uint32_t)__cvta_generic_to_shared(smem);

    int lrow[4], luc[4];
    uint32_t s_off[4];
    bool predA[4], predB[4];
    const __nv_bfloat16* srcA[4];
    const __nv_bfloat16* srcB[4];
    #pragma unroll
    for (int i = 0; i < 4; i++) {
        int u = tid + 256 * i;
        lrow[i] = u >> 3; luc[i] = u & 7;
        s_off[i] = (uint32_t)(lrow[i] * 128 + ((luc[i] ^ (lrow[i] & 7)) << 4));
        int gm = blk_m + lrow[i];
        predA[i] = gm < M;
        srcA[i] = j.A + (size_t)(predA[i] ? gm : 0) * KHL + luc[i] * 8;
        int gn = blk_n + lrow[i];
        predB[i] = gn < j.N;
        srcB[i] = j.Bw + (size_t)(predB[i] ? gn : 0) * KHL + luc[i] * 8;
    }

    float acc[2][8][4];
    #pragma unroll
    for (int a = 0; a < 2; a++)
        #pragma unroll
        for (int b = 0; b < 8; b++)
            #pragma unroll
            for (int c = 0; c < 4; c++) acc[a][b][c] = 0.f;

    auto issue = [&](int c, int buf) {
        int pass = c >> 2, kk = (c & 3) * 64;
        int acol = ((pass == 2) ? DMODEL : 0) + kk;
        int bcol = ((pass == 1) ? DMODEL : 0) + kk;
        uint32_t abase = s_base + buf * 32768;
        uint32_t bbase = abase + 16384;
        #pragma unroll
        for (int i = 0; i < 4; i++) {
            cp_async16(abase + s_off[i], srcA[i] + acol, predA[i]);
            cp_async16(bbase + s_off[i], srcB[i] + bcol, predB[i]);
        }
        asm volatile("cp.async.commit_group;" ::: "memory");
    };

    issue(0, 0);

    for (int c = 0; c < 12; c++) {
        if (c + 1 < 12) {
            issue(c + 1, (c + 1) & 1);
            asm volatile("cp.async.wait_group 1;" ::: "memory");
        } else {
            asm volatile("cp.async.wait_group 0;" ::: "memory");
        }
        __syncthreads();

        const uint32_t abase = s_base + (c & 1) * 32768;
        const uint32_t bbase = abase + 16384;

        #pragma unroll
        for (int ks = 0; ks < 4; ks++) {
            uint32_t af[2][4];
            #pragma unroll
            for (int mi = 0; mi < 2; mi++) {
                int row = warp_m * 32 + mi * 16 + (t4 & 1) * 8 + r8;
                int kch = ks * 2 + (t4 >> 1);
                uint32_t addr = abase + (uint32_t)(row * 128 + ((kch ^ (row & 7)) << 4));
                asm volatile("ldmatrix.sync.aligned.m8n8.x4.shared.b16 {%0,%1,%2,%3}, [%4];"
                             : "=r"(af[mi][0]), "=r"(af[mi][1]), "=r"(af[mi][2]), "=r"(af[mi][3])
                             : "r"(addr));
            }
            uint32_t bf[4][4];
            #pragma unroll
            for (int jj = 0; jj < 4; jj++) {
                int nrow = warp_n * 64 + jj * 16 + (t4 >> 1) * 8 + r8;
                int kch = ks * 2 + (t4 & 1);
                uint32_t addr = bbase + (uint32_t)(nrow * 128 + ((kch ^ (nrow & 7)) << 4));
                asm volatile("ldmatrix.sync.aligned.m8n8.x4.shared.b16 {%0,%1,%2,%3}, [%4];"
                             : "=r"(bf[jj][0]), "=r"(bf[jj][1]), "=r"(bf[jj][2]), "=r"(bf[jj][3])
                             : "r"(addr));
            }
            #pragma unroll
            for (int mi = 0; mi < 2; mi++)
                #pragma unroll
                for (int nj = 0; nj < 8; nj++) {
                    uint32_t b0 = bf[nj >> 1][(nj & 1) * 2 + 0];
                    uint32_t b1 = bf[nj >> 1][(nj & 1) * 2 + 1];
                    asm volatile(
                        "mma.sync.aligned.m16n8k16.row.col.f32.bf16.bf16.f32 "
                        "{%0,%1,%2,%3}, {%4,%5,%6,%7}, {%8,%9}, {%0,%1,%2,%3};"
                        : "+f"(acc[mi][nj][0]), "+f"(acc[mi][nj][1]),
                          "+f"(acc[mi][nj][2]), "+f"(acc[mi][nj][3])
                        : "r"(af[mi][0]), "r"(af[mi][1]), "r"(af[mi][2]), "r"(af[mi][3]),
                          "r"(b0), "r"(b1));
                }
        }
        __syncthreads();
    }

    // epilogue
    const int g = lane >> 2, tg = lane & 3;
    #pragma unroll
    for (int mi = 0; mi < 2; mi++) {
        int row0 = blk_m + warp_m * 32 + mi * 16 + g;
        #pragma unroll
        for (int nj = 0; nj < 8; nj++) {
            int col = blk_n + warp_n * 64 + nj * 8 + tg * 2;
            if (col >= j.N) continue;
            float b0 = __ldg(j.bias + col), b1 = __ldg(j.bias + col + 1);
            if (j.out_half) {
                __half* C = (__half*)j.C;
                if (row0 < M) {
                    __half2 o = __floats2half2_rn(acc[mi][nj][0] + b0, acc[mi][nj][1] + b1);
                    *(__half2*)(C + (size_t)row0 * j.N + col) = o;
                }
                if (row0 + 8 < M) {
                    __half2 o = __floats2half2_rn(acc[mi][nj][2] + b0, acc[mi][nj][3] + b1);
                    *(__half2*)(C + (size_t)(row0 + 8) * j.N + col) = o;
                }
            } else {
                float* C = (float*)j.C;
                if (row0 < M) {
                    float2 o = make_float2(acc[mi][nj][0] + b0, acc[mi][nj][1] + b1);
                    *(float2*)(C + (size_t)row0 * j.N + col) = o;
                }
                if (row0 + 8 < M) {
                    float2 o = make_float2(acc[mi][nj][2] + b0, acc[mi][nj][3] + b1);
                    *(float2*)(C + (size_t)(row0 + 8) * j.N + col) = o;
                }
            }
        }
    }
}

// ---------------- sampling ----------------
// Phase 1 (setup): warp h computes softmax + 4 tap indices/weights for its 12 points.
// Phase 2 (gather): warp w handles HEAD PAIR (w&3) and POINT HALF (w>>2);
//   lanes 0-15 -> head 2p (channel pair = lane), lanes 16-31 -> head 2p+1.
//   One __half2 LDG per lane serves 2 channels. Partials combined via smem.
__global__ __launch_bounds__(256) void sample_kernel(
    const __half* __restrict__ value,      // [SEQ, 256] fp16
    const float* __restrict__ raw,         // [SEQ, 288]
    const float* __restrict__ refp,        // [SEQ, 3, 2]
    __nv_bfloat16* __restrict__ outb,      // [SEQ, 512] hi|lo
    float* __restrict__ attn_out)          // [SEQ, 8, 12] or null
{
    const int q    = blockIdx.x;
    const int tid  = threadIdx.x;
    const int head = tid >> 5;
    const int lane = tid & 31;

    __shared__ __align__(16) int   s_idx[NATT][4];
    __shared__ __align__(16) float s_w  [NATT][4];
    __shared__ __align__(16) float s_part[2][DMODEL];

    const float* rq = raw + (size_t)q * N2;

    // ---- phase 1: softmax + tap setup (warp = head) ----
    float logit = (lane < LP) ? rq[NOFF + head * LP + lane] : -INFINITY;
    float m = logit;
    #pragma unroll
    for (int o = 16; o; o >>= 1) m = fmaxf(m, __shfl_xor_sync(0xffffffffu, m, o));
    float e = (lane < LP) ? expf(logit - m) : 0.f;
    float s = e;
    #pragma unroll
    for (int o = 16; o; o >>= 1) s += __shfl_xor_sync(0xffffffffu, s, o);
    float a = e / s;

    if (lane < LP) {
        if (attn_out) attn_out[((size_t)q * NHEADS + head) * LP + lane] = a;

        const int l = lane >> 2;
        const int Wi = 160 >> l;
        const int start = (l == 0) ? 0 : ((l == 1) ? 25600 : 32000);
        const float dim = (float)Wi;

        const float ox = rq[(head * LP + lane) * 2 + 0];
        const float oy = rq[(head * LP + lane) * 2 + 1];
        const float rx = refp[((size_t)q * NLEVELS + l) * 2 + 0];
        const float ry = refp[((size_t)q * NLEVELS + l) * 2 + 1];
        const float px = (rx + ox / dim) * dim - 0.5f;
        const float py = (ry + oy / dim) * dim - 0.5f;

        const float x0f = floorf(px), y0f = floorf(py);
        const int   x0  = (int)x0f,   y0  = (int)y0f;
        const float wx1 = px - x0f, wy1 = py - y0f;
        const float wx0 = 1.f - wx1, wy0 = 1.f - wy1;

        const bool xok0 = (x0 >= 0)  && (x0 < Wi);
        const bool xok1 = (x0 >= -1) && (x0 + 1 < Wi);
        const bool yok0 = (y0 >= 0)  && (y0 < Wi);
        const bool yok1 = (y0 >= -1) && (y0 + 1 < Wi);

        const int base = start * DMODEL;
        const int r0 = y0 * Wi + x0;
        const int slot = head * LP + lane;

        s_idx[slot][0] = (xok0 && yok0) ? base + r0 * DMODEL            : 0;
        s_idx[slot][1] = (xok1 && yok0) ? base + (r0 + 1) * DMODEL      : 0;
        s_idx[slot][2] = (xok0 && yok1) ? base + (r0 + Wi) * DMODEL     : 0;
        s_idx[slot][3] = (xok1 && yok1) ? base + (r0 + Wi + 1) * DMODEL : 0;
        s_w[slot][0] = (xok0 && yok0) ? a * wy0 * wx0 : 0.f;
        s_w[slot][1] = (xok1 && yok0) ? a * wy0 * wx1 : 0.f;
        s_w[slot][2] = (xok0 && yok1) ? a * wy1 * wx0 : 0.f;
        s_w[slot][3] = (xok1 && yok1) ? a * wy1 * wx1 : 0.f;
    }
    __syncthreads();

    // ---- phase 2: gather (warp = head pair x point half) ----
    {
        const int wid   = tid >> 5;
        const int pairh = (wid & 3) * 2 + (lane >> 4);   // my head
        const int phalf = wid >> 2;                       // points [phalf*6, phalf*6+6)
        const int ch2   = lane & 15;                      // channel pair idx (2 ch)
        const __half2* vb = (const __half2*)(value + pairh * HD + ch2 * 2);

        float2 acc = make_float2(0.f, 0.f);
        const int slot0 = pairh * LP + phalf * 6;
        #pragma unroll
        for (int p = 0; p < 6; p++) {
            const int4   I  = *reinterpret_cast<const int4*>(s_idx[slot0 + p]);
            const float4 W4 = *reinterpret_cast<const float4*>(s_w[slot0 + p]);
            float2 f0 = __half22float2(__ldg((const __half2*)((const __half*)vb + I.x)));
            float2 f1 = __half22float2(__ldg((const __half2*)((const __half*)vb + I.y)));
            float2 f2 = __half22float2(__ldg((const __half2*)((const __half*)vb + I.z)));
            float2 f3 = __half22float2(__ldg((const __half2*)((const __half*)vb + I.w)));
            acc.x = fmaf(W4.x, f0.x, acc.x); acc.y = fmaf(W4.x, f0.y, acc.y);
            acc.x = fmaf(W4.y, f1.x, acc.x); acc.y = fmaf(W4.y, f1.y, acc.y);
            acc.x = fmaf(W4.z, f2.x, acc.x); acc.y = fmaf(W4.z, f2.y, acc.y);
            acc.x = fmaf(W4.w, f3.x, acc.x); acc.y = fmaf(W4.w, f3.y, acc.y);
        }
        *(float2*)&s_part[phalf][pairh * HD + ch2 * 2] = acc;
    }
    __syncthreads();

    // ---- phase 3: combine + hi/lo output ----
    {
        float o = s_part[0][tid] + s_part[1][tid];
        __nv_bfloat16 hi, lo;
        split_bf16(o, hi, lo);
        outb[(size_t)q * KHL + tid]          = hi;
        outb[(size_t)q * KHL + DMODEL + tid] = lo;
    }
}

// ---------------- launch ----------------
extern "C" void kernel_launch(void* const* d_in, const int* in_sizes, int n_in,
                              void* d_out, int out_size)
{
    const float* hidden = (const float*)d_in[0];
    const float* enc    = (const float*)d_in[1];
    const float* pos    = (const float*)d_in[2];
    const float* refp   = (const float*)d_in[3];
    const float* Wv     = (const float*)d_in[4];
    const float* bv     = (const float*)d_in[5];
    const float* Ws     = (const float*)d_in[6];
    const float* bs     = (const float*)d_in[7];
    const float* Wa     = (const float*)d_in[8];
    const float* ba     = (const float*)d_in[9];
    const float* Wo     = (const float*)d_in[10];
    const float* bo     = (const float*)d_in[11];

    float* out = (float*)d_out;
    float* attn_ptr = ((size_t)out_size >= OUT_ELEMS + ATTN_ELEMS) ? (out + OUT_ELEMS) : nullptr;

    __half* p_valueh; float *p_raw, *p_b2;
    __nv_bfloat16 *p_encb, *p_hsb, *p_sampb, *p_wvb, *p_w2b, *p_wob;
    cudaGetSymbolAddress((void**)&p_valueh, g_valueh);
    cudaGetSymbolAddress((void**)&p_raw,    g_raw);
    cudaGetSymbolAddress((void**)&p_b2,     g_b2);
    cudaGetSymbolAddress((void**)&p_encb,   g_encb);
    cudaGetSymbolAddress((void**)&p_hsb,    g_hsb);
    cudaGetSymbolAddress((void**)&p_sampb,  g_sampb);
    cudaGetSymbolAddress((void**)&p_wvb,    g_wvb);
    cudaGetSymbolAddress((void**)&p_w2b,    g_w2b);
    cudaGetSymbolAddress((void**)&p_wob,    g_wob);

    static bool attr_set = false;
    if (!attr_set) {
        cudaFuncSetAttribute(gemm_kernel, cudaFuncAttributeMaxDynamicSharedMemorySize, 65536);
        attr_set = true;
    }

    // 1) weight prep + activation conversion
    prep_kernel<<<100, 256>>>(Wv, Ws, bs, Wa, ba, Wo);
    conv_act_kernel<<<(2 * SEQ * 32 + 255) / 256, 256>>>(enc, hidden, pos);

    const int grid_m = (SEQ + 127) / 128;   // 263

    // 2) fused: value(fp16) = enc@Wv^T + bv  AND  raw = (hidden+pos)@[Ws;Wa]^T + [bs;ba]
    GemmJob jv = { p_encb, p_wvb, bv,   p_valueh, DMODEL, 1 };
    GemmJob jr = { p_hsb,  p_w2b, p_b2, p_raw,    N2,     0 };
    {
        dim3 g(5, grid_m);
        gemm_kernel<<<g, 256, 65536>>>(jv, jr, 2, SEQ);
    }

    // 3) softmax + deformable sampling (emits bf16 hi|lo)
    sample_kernel<<<SEQ, 256>>>(p_valueh, p_raw, refp, p_sampb, attn_ptr);

    // 4) output = samp @ Wo^T + bo
    GemmJob jo = { p_sampb, p_wob, bo, out, DMODEL, 0 };
    {
        dim3 g(2, grid_m);
        gemm_kernel<<<g, 256, 65536>>>(jo, jo, 2, SEQ);
    }
}

// round 8
// speedup vs baseline: 1.5253x; 1.0214x over previous
#include <cuda_runtime.h>
#include <cuda_bf16.h>
#include <cuda_fp16.h>
#include <math.h>
#include <stddef.h>
#include <stdint.h>

// ---------------- problem constants ----------------
#define SEQ      33600
#define DMODEL   256
#define NHEADS   8
#define NLEVELS  3
#define NPOINTS  4
#define LP       (NLEVELS * NPOINTS)        // 12
#define HD       (DMODEL / NHEADS)          // 32
#define NOFF     (NHEADS * LP * 2)          // 192
#define NATT     (NHEADS * LP)              // 96
#define N2       (NOFF + NATT)              // 288
#define KHL      512                         // hi|lo width
#define OUT_ELEMS  ((size_t)SEQ * DMODEL)
#define ATTN_ELEMS ((size_t)SEQ * NHEADS * LP)

// ---------------- scratch (device globals) ----------------
__device__ __half g_valueh[SEQ * DMODEL];         // value in fp16 (for sampling)
__device__ float  g_raw  [SEQ * N2];
__device__ float  g_b2   [N2];
__device__ __nv_bfloat16 g_encb [SEQ * KHL];      // enc        hi|lo
__device__ __nv_bfloat16 g_hsb  [SEQ * KHL];      // hidden+pos hi|lo
__device__ __nv_bfloat16 g_sampb[SEQ * KHL];      // sampled    hi|lo
__device__ __nv_bfloat16 g_wvb[DMODEL * KHL];
__device__ __nv_bfloat16 g_w2b[N2 * KHL];
__device__ __nv_bfloat16 g_wob[DMODEL * KHL];

// ---------------- helpers ----------------
__device__ __forceinline__ uint32_t pack_bf2(__nv_bfloat16 a, __nv_bfloat16 b) {
    __nv_bfloat162 t = __halves2bfloat162(a, b);
    return *reinterpret_cast<uint32_t*>(&t);
}
__device__ __forceinline__ void split_bf16(float x, __nv_bfloat16& h, __nv_bfloat16& l) {
    h = __float2bfloat16_rn(x);
    l = __float2bfloat16_rn(x - __bfloat162float(h));
}
__device__ __forceinline__ void cvt8(float4 a, float4 b, uint4& H, uint4& L) {
    __nv_bfloat16 h[8], l[8];
    split_bf16(a.x, h[0], l[0]); split_bf16(a.y, h[1], l[1]);
    split_bf16(a.z, h[2], l[2]); split_bf16(a.w, h[3], l[3]);
    split_bf16(b.x, h[4], l[4]); split_bf16(b.y, h[5], l[5]);
    split_bf16(b.z, h[6], l[6]); split_bf16(b.w, h[7], l[7]);
    H = make_uint4(pack_bf2(h[0],h[1]), pack_bf2(h[2],h[3]), pack_bf2(h[4],h[5]), pack_bf2(h[6],h[7]));
    L = make_uint4(pack_bf2(l[0],l[1]), pack_bf2(l[2],l[3]), pack_bf2(l[4],l[5]), pack_bf2(l[6],l[7]));
}
__device__ __forceinline__ void cp_async16(uint32_t dst, const void* src, bool pred) {
    int sz = pred ? 16 : 0;
    asm volatile("cp.async.cg.shared.global [%0], [%1], 16, %2;"
                 :: "r"(dst), "l"(src), "r"(sz) : "memory");
}
// packed f32x2 helpers (PTX ISA 8.6, sm_100+ base feature)
__device__ __forceinline__ unsigned long long pack_f32x2(float lo, float hi) {
    unsigned long long r;
    asm("mov.b64 %0, {%1, %2};" : "=l"(r) : "f"(lo), "f"(hi));
    return r;
}
__device__ __forceinline__ void unpack_f32x2(unsigned long long v, float& lo, float& hi) {
    asm("mov.b64 {%0, %1}, %2;" : "=f"(lo), "=f"(hi) : "l"(v));
}
__device__ __forceinline__ void fma_f32x2(unsigned long long& d,
                                          unsigned long long a, unsigned long long b) {
    asm("fma.rn.f32x2 %0, %1, %2, %0;" : "+l"(d) : "l"(a), "l"(b));
}

// ---------------- weight prep: fp32 -> bf16 hi|lo + b2 ----------------
__global__ __launch_bounds__(256) void prep_kernel(
    const float* __restrict__ Wv, const float* __restrict__ Ws, const float* __restrict__ bs,
    const float* __restrict__ Wa, const float* __restrict__ ba, const float* __restrict__ Wo)
{
    int u = blockIdx.x * 256 + threadIdx.x;     // one unit = 8 floats
    const int TOTAL_ROWS = DMODEL + N2 + DMODEL;  // 800
    if (u < TOTAL_ROWS * 32) {
        int row = u >> 5, uc = u & 31;
        const float* src;
        __nv_bfloat16* dst;
        if (row < DMODEL) { src = Wv + (size_t)row * DMODEL; dst = g_wvb + (size_t)row * KHL; }
        else if (row < DMODEL + N2) {
            int n = row - DMODEL;
            src = (n < NOFF) ? (Ws + (size_t)n * DMODEL) : (Wa + (size_t)(n - NOFF) * DMODEL);
            dst = g_w2b + (size_t)n * KHL;
        } else {
            int n = row - DMODEL - N2;
            src = Wo + (size_t)n * DMODEL; dst = g_wob + (size_t)n * KHL;
        }
        float4 a = *(const float4*)(src + uc * 8);
        float4 b = *(const float4*)(src + uc * 8 + 4);
        uint4 H, L; cvt8(a, b, H, L);
        *(uint4*)(dst + uc * 8)          = H;
        *(uint4*)(dst + DMODEL + uc * 8) = L;
    }
    if (u < N2) g_b2[u] = (u < NOFF) ? bs[u] : ba[u - NOFF];
}

// ---------------- activation conversion: enc and hidden+pos -> bf16 hi|lo ----------------
__global__ __launch_bounds__(256) void conv_act_kernel(
    const float* __restrict__ enc, const float* __restrict__ hidden, const float* __restrict__ pos)
{
    int u = blockIdx.x * 256 + threadIdx.x;
    const int PER = SEQ * 32;                 // units per tensor (8 floats each)
    if (u >= 2 * PER) return;
    bool second = (u >= PER);
    int v = second ? (u - PER) : u;
    int row = v >> 5, uc = v & 31;
    const float* src = (second ? hidden : enc) + (size_t)row * DMODEL + uc * 8;
    float4 a = *(const float4*)(src);
    float4 b = *(const float4*)(src + 4);
    if (second) {
        const float* p2 = pos + (size_t)row * DMODEL + uc * 8;
        float4 u0 = *(const float4*)p2, u1 = *(const float4*)(p2 + 4);
        a.x += u0.x; a.y += u0.y; a.z += u0.z; a.w += u0.w;
        b.x += u1.x; b.y += u1.y; b.z += u1.z; b.w += u1.w;
    }
    uint4 H, L; cvt8(a, b, H, L);
    __nv_bfloat16* dst = (second ? g_hsb : g_encb) + (size_t)row * KHL;
    *(uint4*)(dst + uc * 8)          = H;
    *(uint4*)(dst + DMODEL + uc * 8) = L;
}

// ---------------- GEMM: C[M,N] = A @ Bw^T + bias (compensated bf16, cp.async) ----------------
struct GemmJob {
    const __nv_bfloat16* A;
    const __nv_bfloat16* Bw;
    const float* bias;
    void* C;
    int N;
    int out_half;   // 1: write __half, 0: write float
};

__global__ __launch_bounds__(256, 2) void gemm_kernel(GemmJob j0, GemmJob j1, int xsplit, int M)
{
    extern __shared__ char smem[];   // 2 x (16KB A + 16KB B) = 64 KB

    const bool first = ((int)blockIdx.x < xsplit);
    GemmJob j = first ? j0 : j1;
    const int nb = first ? blockIdx.x : (blockIdx.x - xsplit);
    const int blk_m = blockIdx.y * 128, blk_n = nb * 128;

    const int tid = threadIdx.x;
    const int wid = tid >> 5, lane = tid & 31;
    const int warp_m = wid & 3, warp_n = wid >> 2;
    const int t4 = lane >> 3, r8 = lane & 7;

    const uint32_t s_base = (uint32_t)__cvta_generic_to_shared(smem);

    int lrow[4], luc[4];
    uint32_t s_off[4];
    bool predA[4], predB[4];
    const __nv_bfloat16* srcA[4];
    const __nv_bfloat16* srcB[4];
    #pragma unroll
    for (int i = 0; i < 4; i++) {
        int u = tid + 256 * i;
        lrow[i] = u >> 3; luc[i] = u & 7;
        s_off[i] = (uint32_t)(lrow[i] * 128 + ((luc[i] ^ (lrow[i] & 7)) << 4));
        int gm = blk_m + lrow[i];
        predA[i] = gm < M;
        srcA[i] = j.A + (size_t)(predA[i] ? gm : 0) * KHL + luc[i] * 8;
        int gn = blk_n + lrow[i];
        predB[i] = gn < j.N;
        srcB[i] = j.Bw + (size_t)(predB[i] ? gn : 0) * KHL + luc[i] * 8;
    }

    float acc[2][8][4];
    #pragma unroll
    for (int a = 0; a < 2; a++)
        #pragma unroll
        for (int b = 0; b < 8; b++)
            #pragma unroll
            for (int c = 0; c < 4; c++) acc[a][b][c] = 0.f;

    auto issue = [&](int c, int buf) {
        int pass = c >> 2, kk = (c & 3) * 64;
        int acol = ((pass == 2) ? DMODEL : 0) + kk;
        int bcol = ((pass == 1) ? DMODEL : 0) + kk;
        uint32_t abase = s_base + buf * 32768;
        uint32_t bbase = abase + 16384;
        #pragma unroll
        for (int i = 0; i < 4; i++) {
            cp_async16(abase + s_off[i], srcA[i] + acol, predA[i]);
            cp_async16(bbase + s_off[i], srcB[i] + bcol, predB[i]);
        }
        asm volatile("cp.async.commit_group;" ::: "memory");
    };

    issue(0, 0);

    for (int c = 0; c < 12; c++) {
        if (c + 1 < 12) {
            issue(c + 1, (c + 1) & 1);
            asm volatile("cp.async.wait_group 1;" ::: "memory");
        } else {
            asm volatile("cp.async.wait_group 0;" ::: "memory");
        }
        __syncthreads();

        const uint32_t abase = s_base + (c & 1) * 32768;
        const uint32_t bbase = abase + 16384;

        #pragma unroll
        for (int ks = 0; ks < 4; ks++) {
            uint32_t af[2][4];
            #pragma unroll
            for (int mi = 0; mi < 2; mi++) {
                int row = warp_m * 32 + mi * 16 + (t4 & 1) * 8 + r8;
                int kch = ks * 2 + (t4 >> 1);
                uint32_t addr = abase + (uint32_t)(row * 128 + ((kch ^ (row & 7)) << 4));
                asm volatile("ldmatrix.sync.aligned.m8n8.x4.shared.b16 {%0,%1,%2,%3}, [%4];"
                             : "=r"(af[mi][0]), "=r"(af[mi][1]), "=r"(af[mi][2]), "=r"(af[mi][3])
                             : "r"(addr));
            }
            uint32_t bf[4][4];
            #pragma unroll
            for (int jj = 0; jj < 4; jj++) {
                int nrow = warp_n * 64 + jj * 16 + (t4 >> 1) * 8 + r8;
                int kch = ks * 2 + (t4 & 1);
                uint32_t addr = bbase + (uint32_t)(nrow * 128 + ((kch ^ (nrow & 7)) << 4));
                asm volatile("ldmatrix.sync.aligned.m8n8.x4.shared.b16 {%0,%1,%2,%3}, [%4];"
                             : "=r"(bf[jj][0]), "=r"(bf[jj][1]), "=r"(bf[jj][2]), "=r"(bf[jj][3])
                             : "r"(addr));
            }
            #pragma unroll
            for (int mi = 0; mi < 2; mi++)
                #pragma unroll
                for (int nj = 0; nj < 8; nj++) {
                    uint32_t b0 = bf[nj >> 1][(nj & 1) * 2 + 0];
                    uint32_t b1 = bf[nj >> 1][(nj & 1) * 2 + 1];
                    asm volatile(
                        "mma.sync.aligned.m16n8k16.row.col.f32.bf16.bf16.f32 "
                        "{%0,%1,%2,%3}, {%4,%5,%6,%7}, {%8,%9}, {%0,%1,%2,%3};"
                        : "+f"(acc[mi][nj][0]), "+f"(acc[mi][nj][1]),
                          "+f"(acc[mi][nj][2]), "+f"(acc[mi][nj][3])
                        : "r"(af[mi][0]), "r"(af[mi][1]), "r"(af[mi][2]), "r"(af[mi][3]),
                          "r"(b0), "r"(b1));
                }
        }
        __syncthreads();
    }

    // epilogue
    const int g = lane >> 2, tg = lane & 3;
    #pragma unroll
    for (int mi = 0; mi < 2; mi++) {
        int row0 = blk_m + warp_m * 32 + mi * 16 + g;
        #pragma unroll
        for (int nj = 0; nj < 8; nj++) {
            int col = blk_n + warp_n * 64 + nj * 8 + tg * 2;
            if (col >= j.N) continue;
            float b0 = __ldg(j.bias + col), b1 = __ldg(j.bias + col + 1);
            if (j.out_half) {
                __half* C = (__half*)j.C;
                if (row0 < M) {
                    __half2 o = __floats2half2_rn(acc[mi][nj][0] + b0, acc[mi][nj][1] + b1);
                    *(__half2*)(C + (size_t)row0 * j.N + col) = o;
                }
                if (row0 + 8 < M) {
                    __half2 o = __floats2half2_rn(acc[mi][nj][2] + b0, acc[mi][nj][3] + b1);
                    *(__half2*)(C + (size_t)(row0 + 8) * j.N + col) = o;
                }
            } else {
                float* C = (float*)j.C;
                if (row0 < M) {
                    float2 o = make_float2(acc[mi][nj][0] + b0, acc[mi][nj][1] + b1);
                    *(float2*)(C + (size_t)row0 * j.N + col) = o;
                }
                if (row0 + 8 < M) {
                    float2 o = make_float2(acc[mi][nj][2] + b0, acc[mi][nj][3] + b1);
                    *(float2*)(C + (size_t)(row0 + 8) * j.N + col) = o;
                }
            }
        }
    }
}

// ---------------- sampling: 8 queries per block, warp = query ----------------
// Stage 1: 64 threads do per-(q,head) softmax into s_attn.
// Stage 2: 768 (q,head,point) slots precompute 4 tap byte-offsets + weights into
//          head-minor smem (conflict-free broadcast in gather).
// Stage 3: warp = query; lane = (head=lane>>2, oct=lane&3) owns 8 channels.
//          One warp-LDG.128 per tap = full 512B value row, perfectly coalesced.
//          No cross-lane reduction. Packed f32x2 FMA accumulate.
__global__ __launch_bounds__(256) void sample_kernel(
    const __half* __restrict__ value,      // [SEQ, 256] fp16
    const float* __restrict__ raw,         // [SEQ, 288]
    const float* __restrict__ refp,        // [SEQ, 3, 2]
    __nv_bfloat16* __restrict__ outb,      // [SEQ, 512] hi|lo
    float* __restrict__ attn_out)          // [SEQ, 8, 12] or null
{
    const int q0  = blockIdx.x * 8;
    const int tid = threadIdx.x;

    __shared__ float s_attn[64][LP];            // [q*8+h][p]
    __shared__ int   s_boff[8][48][NHEADS];     // [q][p*4+tap][head] byte offsets
    __shared__ float s_wt  [8][48][NHEADS];

    // ---- stage 1: softmax ----
    if (tid < 64) {
        int q = tid >> 3, h = tid & 7;
        const float* lg = raw + (size_t)(q0 + q) * N2 + NOFF + h * LP;
        float l[LP]; float m = -INFINITY;
        #pragma unroll
        for (int p = 0; p < LP; p++) { l[p] = lg[p]; m = fmaxf(m, l[p]); }
        float s = 0.f;
        #pragma unroll
        for (int p = 0; p < LP; p++) { l[p] = expf(l[p] - m); s += l[p]; }
        float inv = 1.f / s;
        #pragma unroll
        for (int p = 0; p < LP; p++) s_attn[q * 8 + h][p] = l[p] * inv;
    }
    __syncthreads();

    // ---- stage 2: tap setup (768 slots, 3 per thread) ----
    #pragma unroll
    for (int i = 0; i < 3; i++) {
        int s = i * 256 + tid;
        int q = s / 96; int rem = s - q * 96;
        int h = rem / LP; int p = rem - h * LP;

        float a = s_attn[q * 8 + h][p];
        if (attn_out) attn_out[((size_t)(q0 + q) * NHEADS + h) * LP + p] = a;

        const float* rq = raw + (size_t)(q0 + q) * N2;
        float2 off = *(const float2*)(rq + (h * LP + p) * 2);
        int lvl = p >> 2;
        int Wi = 160 >> lvl;
        int start = (lvl == 0) ? 0 : ((lvl == 1) ? 25600 : 32000);
        float dim = (float)Wi;
        float2 rp = *(const float2*)(refp + ((size_t)(q0 + q) * NLEVELS + lvl) * 2);

        float px = (rp.x + off.x / dim) * dim - 0.5f;
        float py = (rp.y + off.y / dim) * dim - 0.5f;

        float x0f = floorf(px), y0f = floorf(py);
        int x0 = (int)x0f, y0 = (int)y0f;
        float wx1 = px - x0f, wy1 = py - y0f;
        float wx0 = 1.f - wx1, wy0 = 1.f - wy1;

        bool xok0 = (x0 >= 0)  && (x0 < Wi);
        bool xok1 = (x0 >= -1) && (x0 + 1 < Wi);
        bool yok0 = (y0 >= 0)  && (y0 < Wi);
        bool yok1 = (y0 >= -1) && (y0 + 1 < Wi);

        int r0 = start + y0 * Wi + x0;       // element-row index
        int slot = p * 4;
        // byte offset = row * 256 ch * 2 B = row * 512
        s_boff[q][slot + 0][h] = (xok0 && yok0) ? (r0) * 512            : 0;
        s_boff[q][slot + 1][h] = (xok1 && yok0) ? (r0 + 1) * 512        : 0;
        s_boff[q][slot + 2][h] = (xok0 && yok1) ? (r0 + Wi) * 512       : 0;
        s_boff[q][slot + 3][h] = (xok1 && yok1) ? (r0 + Wi + 1) * 512   : 0;
        s_wt[q][slot + 0][h] = (xok0 && yok0) ? a * wy0 * wx0 : 0.f;
        s_wt[q][slot + 1][h] = (xok1 && yok0) ? a * wy0 * wx1 : 0.f;
        s_wt[q][slot + 2][h] = (xok0 && yok1) ? a * wy1 * wx0 : 0.f;
        s_wt[q][slot + 3][h] = (xok1 && yok1) ? a * wy1 * wx1 : 0.f;
    }
    __syncthreads();

    // ---- stage 3: gather ----
    {
        const int wq   = tid >> 5;          // query within block
        const int lane = tid & 31;
        const int h    = lane >> 2;         // head
        const int oct  = lane & 3;          // channel octet (8 ch)

        const char* vbase = (const char*)value + h * 64 + oct * 16;
        const int*   bp = &s_boff[wq][0][h];
        const float* wp = &s_wt  [wq][0][h];

        unsigned long long acc0 = 0, acc1 = 0, acc2 = 0, acc3 = 0;

        for (int pt = 0; pt < LP; pt++) {
            #pragma unroll
            for (int t = 0; t < 4; t++) {
                int it = pt * 4 + t;
                int bo  = bp[it * NHEADS];
                float w = wp[it * NHEADS];
                unsigned long long wp2 = pack_f32x2(w, w);
                uint4 v = __ldg((const uint4*)(vbase + bo));
                float2 f0 = __half22float2(*reinterpret_cast<__half2*>(&v.x));
                float2 f1 = __half22float2(*reinterpret_cast<__half2*>(&v.y));
                float2 f2 = __half22float2(*reinterpret_cast<__half2*>(&v.z));
                float2 f3 = __half22float2(*reinterpret_cast<__half2*>(&v.w));
                fma_f32x2(acc0, pack_f32x2(f0.x, f0.y), wp2);
                fma_f32x2(acc1, pack_f32x2(f1.x, f1.y), wp2);
                fma_f32x2(acc2, pack_f32x2(f2.x, f2.y), wp2);
                fma_f32x2(acc3, pack_f32x2(f3.x, f3.y), wp2);
            }
        }

        // write 8 channels: hi/lo bf16
        float f[8];
        unpack_f32x2(acc0, f[0], f[1]);
        unpack_f32x2(acc1, f[2], f[3]);
        unpack_f32x2(acc2, f[4], f[5]);
        unpack_f32x2(acc3, f[6], f[7]);
        __nv_bfloat16 hi[8], lo[8];
        #pragma unroll
        for (int k = 0; k < 8; k++) split_bf16(f[k], hi[k], lo[k]);
        uint4 HI = make_uint4(pack_bf2(hi[0],hi[1]), pack_bf2(hi[2],hi[3]),
                              pack_bf2(hi[4],hi[5]), pack_bf2(hi[6],hi[7]));
        uint4 LO = make_uint4(pack_bf2(lo[0],lo[1]), pack_bf2(lo[2],lo[3]),
                              pack_bf2(lo[4],lo[5]), pack_bf2(lo[6],lo[7]));
        size_t orow = (size_t)(q0 + wq) * KHL + h * HD + oct * 8;
        *(uint4*)(outb + orow)          = HI;
        *(uint4*)(outb + orow + DMODEL) = LO;
    }
}

// ---------------- launch ----------------
extern "C" void kernel_launch(void* const* d_in, const int* in_sizes, int n_in,
                              void* d_out, int out_size)
{
    const float* hidden = (const float*)d_in[0];
    const float* enc    = (const float*)d_in[1];
    const float* pos    = (const float*)d_in[2];
    const float* refp   = (const float*)d_in[3];
    const float* Wv     = (const float*)d_in[4];
    const float* bv     = (const float*)d_in[5];
    const float* Ws     = (const float*)d_in[6];
    const float* bs     = (const float*)d_in[7];
    const float* Wa     = (const float*)d_in[8];
    const float* ba     = (const float*)d_in[9];
    const float* Wo     = (const float*)d_in[10];
    const float* bo     = (const float*)d_in[11];

    float* out = (float*)d_out;
    float* attn_ptr = ((size_t)out_size >= OUT_ELEMS + ATTN_ELEMS) ? (out + OUT_ELEMS) : nullptr;

    __half* p_valueh; float *p_raw, *p_b2;
    __nv_bfloat16 *p_encb, *p_hsb, *p_sampb, *p_wvb, *p_w2b, *p_wob;
    cudaGetSymbolAddress((void**)&p_valueh, g_valueh);
    cudaGetSymbolAddress((void**)&p_raw,    g_raw);
    cudaGetSymbolAddress((void**)&p_b2,     g_b2);
    cudaGetSymbolAddress((void**)&p_encb,   g_encb);
    cudaGetSymbolAddress((void**)&p_hsb,    g_hsb);
    cudaGetSymbolAddress((void**)&p_sampb,  g_sampb);
    cudaGetSymbolAddress((void**)&p_wvb,    g_wvb);
    cudaGetSymbolAddress((void**)&p_w2b,    g_w2b);
    cudaGetSymbolAddress((void**)&p_wob,    g_wob);

    static bool attr_set = false;
    if (!attr_set) {
        cudaFuncSetAttribute(gemm_kernel, cudaFuncAttributeMaxDynamicSharedMemorySize, 65536);
        attr_set = true;
    }

    // 1) weight prep + activation conversion
    prep_kernel<<<100, 256>>>(Wv, Ws, bs, Wa, ba, Wo);
    conv_act_kernel<<<(2 * SEQ * 32 + 255) / 256, 256>>>(enc, hidden, pos);

    const int grid_m = (SEQ + 127) / 128;   // 263

    // 2) fused: value(fp16) = enc@Wv^T + bv  AND  raw = (hidden+pos)@[Ws;Wa]^T + [bs;ba]
    GemmJob jv = { p_encb, p_wvb, bv,   p_valueh, DMODEL, 1 };
    GemmJob jr = { p_hsb,  p_w2b, p_b2, p_raw,    N2,     0 };
    {
        dim3 g(5, grid_m);
        gemm_kernel<<<g, 256, 65536>>>(jv, jr, 2, SEQ);
    }

    // 3) softmax + deformable sampling (emits bf16 hi|lo), 8 queries per block
    sample_kernel<<<SEQ / 8, 256>>>(p_valueh, p_raw, refp, p_sampb, attn_ptr);

    // 4) output = samp @ Wo^T + bo
    GemmJob jo = { p_sampb, p_wob, bo, out, DMODEL, 0 };
    {
        dim3 g(2, grid_m);
        gemm_kernel<<<g, 256, 65536>>>(jo, jo, 2, SEQ);
    }
}

// round 9
// speedup vs baseline: 1.7221x; 1.1291x over previous
#include <cuda_runtime.h>
#include <cuda_bf16.h>
#include <cuda_fp16.h>
#include <math.h>
#include <stddef.h>
#include <stdint.h>

// ---------------- problem constants ----------------
#define SEQ      33600
#define DMODEL   256
#define NHEADS   8
#define NLEVELS  3
#define NPOINTS  4
#define LP       (NLEVELS * NPOINTS)        // 12
#define HD       (DMODEL / NHEADS)          // 32
#define NOFF     (NHEADS * LP * 2)          // 192
#define NATT     (NHEADS * LP)              // 96
#define N2       (NOFF + NATT)              // 288
#define KHL      512                         // hi|lo width
#define VROWS    (SEQ + 4)                   // padded rows per head
#define COPY_ELEMS ((size_t)NHEADS * VROWS * HD)      // halves per copy
#define COPYSZB  ((int)(COPY_ELEMS * 2))              // bytes per copy
#define OUT_ELEMS  ((size_t)SEQ * DMODEL)
#define ATTN_ELEMS ((size_t)SEQ * NHEADS * LP)

// ---------------- scratch (device globals) ----------------
__device__ __half g_val2[2 * COPY_ELEMS];         // value, head-major, copies A|B(shifted)
__device__ float  g_raw  [SEQ * N2];
__device__ float  g_b2   [N2];
__device__ __nv_bfloat16 g_encb [SEQ * KHL];      // enc        hi|lo
__device__ __nv_bfloat16 g_hsb  [SEQ * KHL];      // hidden+pos hi|lo
__device__ __nv_bfloat16 g_sampb[SEQ * KHL];      // sampled    hi|lo
__device__ __nv_bfloat16 g_wvb[DMODEL * KHL];
__device__ __nv_bfloat16 g_w2b[N2 * KHL];
__device__ __nv_bfloat16 g_wob[DMODEL * KHL];

// ---------------- helpers ----------------
__device__ __forceinline__ uint32_t pack_bf2(__nv_bfloat16 a, __nv_bfloat16 b) {
    __nv_bfloat162 t = __halves2bfloat162(a, b);
    return *reinterpret_cast<uint32_t*>(&t);
}
__device__ __forceinline__ void split_bf16(float x, __nv_bfloat16& h, __nv_bfloat16& l) {
    h = __float2bfloat16_rn(x);
    l = __float2bfloat16_rn(x - __bfloat162float(h));
}
__device__ __forceinline__ void cvt8(float4 a, float4 b, uint4& H, uint4& L) {
    __nv_bfloat16 h[8], l[8];
    split_bf16(a.x, h[0], l[0]); split_bf16(a.y, h[1], l[1]);
    split_bf16(a.z, h[2], l[2]); split_bf16(a.w, h[3], l[3]);
    split_bf16(b.x, h[4], l[4]); split_bf16(b.y, h[5], l[5]);
    split_bf16(b.z, h[6], l[6]); split_bf16(b.w, h[7], l[7]);
    H = make_uint4(pack_bf2(h[0],h[1]), pack_bf2(h[2],h[3]), pack_bf2(h[4],h[5]), pack_bf2(h[6],h[7]));
    L = make_uint4(pack_bf2(l[0],l[1]), pack_bf2(l[2],l[3]), pack_bf2(l[4],l[5]), pack_bf2(l[6],l[7]));
}
__device__ __forceinline__ void cp_async16(uint32_t dst, const void* src, bool pred) {
    int sz = pred ? 16 : 0;
    asm volatile("cp.async.cg.shared.global [%0], [%1], 16, %2;"
                 :: "r"(dst), "l"(src), "r"(sz) : "memory");
}
// packed f32x2 helpers (sm_100+ base feature)
__device__ __forceinline__ unsigned long long pack_f32x2(float lo, float hi) {
    unsigned long long r;
    asm("mov.b64 %0, {%1, %2};" : "=l"(r) : "f"(lo), "f"(hi));
    return r;
}
__device__ __forceinline__ void unpack_f32x2(unsigned long long v, float& lo, float& hi) {
    asm("mov.b64 {%0, %1}, %2;" : "=f"(lo), "=f"(hi) : "l"(v));
}
__device__ __forceinline__ void fma_f32x2(unsigned long long& d,
                                          unsigned long long a, unsigned long long b) {
    asm("fma.rn.f32x2 %0, %1, %2, %0;" : "+l"(d) : "l"(a), "l"(b));
}
__device__ __forceinline__ unsigned long long add_f32x2(unsigned long long a, unsigned long long b) {
    unsigned long long r;
    asm("add.rn.f32x2 %0, %1, %2;" : "=l"(r) : "l"(a), "l"(b));
    return r;
}

// ---------------- weight prep: fp32 -> bf16 hi|lo + b2 ----------------
__global__ __launch_bounds__(256) void prep_kernel(
    const float* __restrict__ Wv, const float* __restrict__ Ws, const float* __restrict__ bs,
    const float* __restrict__ Wa, const float* __restrict__ ba, const float* __restrict__ Wo)
{
    int u = blockIdx.x * 256 + threadIdx.x;     // one unit = 8 floats
    const int TOTAL_ROWS = DMODEL + N2 + DMODEL;  // 800
    if (u < TOTAL_ROWS * 32) {
        int row = u >> 5, uc = u & 31;
        const float* src;
        __nv_bfloat16* dst;
        if (row < DMODEL) { src = Wv + (size_t)row * DMODEL; dst = g_wvb + (size_t)row * KHL; }
        else if (row < DMODEL + N2) {
            int n = row - DMODEL;
            src = (n < NOFF) ? (Ws + (size_t)n * DMODEL) : (Wa + (size_t)(n - NOFF) * DMODEL);
            dst = g_w2b + (size_t)n * KHL;
        } else {
            int n = row - DMODEL - N2;
            src = Wo + (size_t)n * DMODEL; dst = g_wob + (size_t)n * KHL;
        }
        float4 a = *(const float4*)(src + uc * 8);
        float4 b = *(const float4*)(src + uc * 8 + 4);
        uint4 H, L; cvt8(a, b, H, L);
        *(uint4*)(dst + uc * 8)          = H;
        *(uint4*)(dst + DMODEL + uc * 8) = L;
    }
    if (u < N2) g_b2[u] = (u < NOFF) ? bs[u] : ba[u - NOFF];
}

// ---------------- activation conversion: enc and hidden+pos -> bf16 hi|lo ----------------
__global__ __launch_bounds__(256) void conv_act_kernel(
    const float* __restrict__ enc, const float* __restrict__ hidden, const float* __restrict__ pos)
{
    int u = blockIdx.x * 256 + threadIdx.x;
    const int PER = SEQ * 32;                 // units per tensor (8 floats each)
    if (u >= 2 * PER) return;
    bool second = (u >= PER);
    int v = second ? (u - PER) : u;
    int row = v >> 5, uc = v & 31;
    const float* src = (second ? hidden : enc) + (size_t)row * DMODEL + uc * 8;
    float4 a = *(const float4*)(src);
    float4 b = *(const float4*)(src + 4);
    if (second) {
        const float* p2 = pos + (size_t)row * DMODEL + uc * 8;
        float4 u0 = *(const float4*)p2, u1 = *(const float4*)(p2 + 4);
        a.x += u0.x; a.y += u0.y; a.z += u0.z; a.w += u0.w;
        b.x += u1.x; b.y += u1.y; b.z += u1.z; b.w += u1.w;
    }
    uint4 H, L; cvt8(a, b, H, L);
    __nv_bfloat16* dst = (second ? g_hsb : g_encb) + (size_t)row * KHL;
    *(uint4*)(dst + uc * 8)          = H;
    *(uint4*)(dst + DMODEL + uc * 8) = L;
}

// ---------------- GEMM: C[M,N] = A @ Bw^T + bias (compensated bf16, cp.async) ----------------
struct GemmJob {
    const __nv_bfloat16* A;
    const __nv_bfloat16* Bw;
    const float* bias;
    void* C;
    int N;
    int out_half;   // 1: write __half head-major dual-copy (value), 0: write float
};

__global__ __launch_bounds__(256, 2) void gemm_kernel(GemmJob j0, GemmJob j1, int xsplit, int M)
{
    extern __shared__ char smem[];   // 2 x (16KB A + 16KB B) = 64 KB

    const bool first = ((int)blockIdx.x < xsplit);
    GemmJob j = first ? j0 : j1;
    const int nb = first ? blockIdx.x : (blockIdx.x - xsplit);
    const int blk_m = blockIdx.y * 128, blk_n = nb * 128;

    const int tid = threadIdx.x;
    const int wid = tid >> 5, lane = tid & 31;
    const int warp_m = wid & 3, warp_n = wid >> 2;
    const int t4 = lane >> 3, r8 = lane & 7;

    const uint32_t s_base = (uint32_t)__cvta_generic_to_shared(smem);

    int lrow[4], luc[4];
    uint32_t s_off[4];
    bool predA[4], predB[4];
    const __nv_bfloat16* srcA[4];
    const __nv_bfloat16* srcB[4];
    #pragma unroll
    for (int i = 0; i < 4; i++) {
        int u = tid + 256 * i;
        lrow[i] = u >> 3; luc[i] = u & 7;
        s_off[i] = (uint32_t)(lrow[i] * 128 + ((luc[i] ^ (lrow[i] & 7)) << 4));
        int gm = blk_m + lrow[i];
        predA[i] = gm < M;
        srcA[i] = j.A + (size_t)(predA[i] ? gm : 0) * KHL + luc[i] * 8;
        int gn = blk_n + lrow[i];
        predB[i] = gn < j.N;
        srcB[i] = j.Bw + (size_t)(predB[i] ? gn : 0) * KHL + luc[i] * 8;
    }

    float acc[2][8][4];
    #pragma unroll
    for (int a = 0; a < 2; a++)
        #pragma unroll
        for (int b = 0; b < 8; b++)
            #pragma unroll
            for (int c = 0; c < 4; c++) acc[a][b][c] = 0.f;

    auto issue = [&](int c, int buf) {
        int pass = c >> 2, kk = (c & 3) * 64;
        int acol = ((pass == 2) ? DMODEL : 0) + kk;
        int bcol = ((pass == 1) ? DMODEL : 0) + kk;
        uint32_t abase = s_base + buf * 32768;
        uint32_t bbase = abase + 16384;
        #pragma unroll
        for (int i = 0; i < 4; i++) {
            cp_async16(abase + s_off[i], srcA[i] + acol, predA[i]);
            cp_async16(bbase + s_off[i], srcB[i] + bcol, predB[i]);
        }
        asm volatile("cp.async.commit_group;" ::: "memory");
    };

    issue(0, 0);

    for (int c = 0; c < 12; c++) {
        if (c + 1 < 12) {
            issue(c + 1, (c + 1) & 1);
            asm volatile("cp.async.wait_group 1;" ::: "memory");
        } else {
            asm volatile("cp.async.wait_group 0;" ::: "memory");
        }
        __syncthreads();

        const uint32_t abase = s_base + (c & 1) * 32768;
        const uint32_t bbase = abase + 16384;

        #pragma unroll
        for (int ks = 0; ks < 4; ks++) {
            uint32_t af[2][4];
            #pragma unroll
            for (int mi = 0; mi < 2; mi++) {
                int row = warp_m * 32 + mi * 16 + (t4 & 1) * 8 + r8;
                int kch = ks * 2 + (t4 >> 1);
                uint32_t addr = abase + (uint32_t)(row * 128 + ((kch ^ (row & 7)) << 4));
                asm volatile("ldmatrix.sync.aligned.m8n8.x4.shared.b16 {%0,%1,%2,%3}, [%4];"
                             : "=r"(af[mi][0]), "=r"(af[mi][1]), "=r"(af[mi][2]), "=r"(af[mi][3])
                             : "r"(addr));
            }
            uint32_t bf[4][4];
            #pragma unroll
            for (int jj = 0; jj < 4; jj++) {
                int nrow = warp_n * 64 + jj * 16 + (t4 >> 1) * 8 + r8;
                int kch = ks * 2 + (t4 & 1);
                uint32_t addr = bbase + (uint32_t)(nrow * 128 + ((kch ^ (nrow & 7)) << 4));
                asm volatile("ldmatrix.sync.aligned.m8n8.x4.shared.b16 {%0,%1,%2,%3}, [%4];"
                             : "=r"(bf[jj][0]), "=r"(bf[jj][1]), "=r"(bf[jj][2]), "=r"(bf[jj][3])
                             : "r"(addr));
            }
            #pragma unroll
            for (int mi = 0; mi < 2; mi++)
                #pragma unroll
                for (int nj = 0; nj < 8; nj++) {
                    uint32_t b0 = bf[nj >> 1][(nj & 1) * 2 + 0];
                    uint32_t b1 = bf[nj >> 1][(nj & 1) * 2 + 1];
                    asm volatile(
                        "mma.sync.aligned.m16n8k16.row.col.f32.bf16.bf16.f32 "
                        "{%0,%1,%2,%3}, {%4,%5,%6,%7}, {%8,%9}, {%0,%1,%2,%3};"
                        : "+f"(acc[mi][nj][0]), "+f"(acc[mi][nj][1]),
                          "+f"(acc[mi][nj][2]), "+f"(acc[mi][nj][3])
                        : "r"(af[mi][0]), "r"(af[mi][1]), "r"(af[mi][2]), "r"(af[mi][3]),
                          "r"(b0), "r"(b1));
                }
        }
        __syncthreads();
    }

    // epilogue
    const int g = lane >> 2, tg = lane & 3;
    #pragma unroll
    for (int mi = 0; mi < 2; mi++) {
        int row0 = blk_m + warp_m * 32 + mi * 16 + g;
        #pragma unroll
        for (int nj = 0; nj < 8; nj++) {
            int col = blk_n + warp_n * 64 + nj * 8 + tg * 2;
            if (col >= j.N) continue;
            float b0 = __ldg(j.bias + col), b1 = __ldg(j.bias + col + 1);
            if (j.out_half) {
                // head-major dual-copy value store
                __half* C = (__half*)j.C;
                int h = col >> 5, ch = col & 31;
                #pragma unroll
                for (int rr = 0; rr < 2; rr++) {
                    int row = row0 + rr * 8;
                    if (row >= M) continue;
                    __half2 o = __floats2half2_rn(acc[mi][nj][rr * 2 + 0] + b0,
                                                  acc[mi][nj][rr * 2 + 1] + b1);
                    size_t eA = ((size_t)h * VROWS + row) * HD + ch;
                    *(__half2*)(C + eA) = o;
                    int slotB = (row == 0) ? (SEQ + 2) : (row - 1);
                    *(__half2*)(C + COPY_ELEMS + ((size_t)h * VROWS + slotB) * HD + ch) = o;
                }
            } else {
                float* C = (float*)j.C;
                if (row0 < M) {
                    float2 o = make_float2(acc[mi][nj][0] + b0, acc[mi][nj][1] + b1);
                    *(float2*)(C + (size_t)row0 * j.N + col) = o;
                }
                if (row0 + 8 < M) {
                    float2 o = make_float2(acc[mi][nj][2] + b0, acc[mi][nj][3] + b1);
                    *(float2*)(C + (size_t)(row0 + 8) * j.N + col) = o;
                }
            }
        }
    }
}

// ---------------- sampling: 8 queries/block, warp=query, pair-aligned gather ----------------
// Value layout: head-major [h][row][32ch] fp16, copy A (base) + copy B (rows shifted -1).
// A tap pair (x0,x0+1) is one ALIGNED 128B line: copy A if r0 even, copy B if r0 odd.
// Stage 2 stores per (q,h,p,ytap): base byte offset + weights for the two 64B halves.
// Stage 3: per point 4 LDG.128; lane = (hgrp via LDG, h0=lane>>3, xhalf=(lane>>2)&1,
// oct=lane&3). shfl_xor(4) combines x-halves at the end.
__global__ __launch_bounds__(256) void sample_kernel(
    const __half* __restrict__ value,      // g_val2
    const float* __restrict__ raw,         // [SEQ, 288]
    const float* __restrict__ refp,        // [SEQ, 3, 2]
    __nv_bfloat16* __restrict__ outb,      // [SEQ, 512] hi|lo
    float* __restrict__ attn_out)          // [SEQ, 8, 12] or null
{
    const int q0  = blockIdx.x * 8;
    const int tid = threadIdx.x;

    __shared__ float s_attn[64][LP];            // [q*8+h][p]
    __shared__ int   s_bo[8][24][NHEADS];       // [q][p*2+ytap][h] byte offset
    __shared__ float s_w [8][24][NHEADS][2];    // weights for the two 64B halves

    // ---- stage 1: softmax ----
    if (tid < 64) {
        int q = tid >> 3, h = tid & 7;
        const float* lg = raw + (size_t)(q0 + q) * N2 + NOFF + h * LP;
        float l[LP]; float m = -INFINITY;
        #pragma unroll
        for (int p = 0; p < LP; p++) { l[p] = lg[p]; m = fmaxf(m, l[p]); }
        float s = 0.f;
        #pragma unroll
        for (int p = 0; p < LP; p++) { l[p] = expf(l[p] - m); s += l[p]; }
        float inv = 1.f / s;
        #pragma unroll
        for (int p = 0; p < LP; p++) s_attn[q * 8 + h][p] = l[p] * inv;
    }
    __syncthreads();

    // ---- stage 2: tap setup (768 slots, 3 per thread) ----
    #pragma unroll
    for (int i = 0; i < 3; i++) {
        int s = i * 256 + tid;
        int q = s / 96; int rem = s - q * 96;
        int h = rem / LP; int p = rem - h * LP;

        float a = s_attn[q * 8 + h][p];
        if (attn_out) attn_out[((size_t)(q0 + q) * NHEADS + h) * LP + p] = a;

        const float* rq = raw + (size_t)(q0 + q) * N2;
        float2 off = *(const float2*)(rq + (h * LP + p) * 2);
        int lvl = p >> 2;
        int Wi = 160 >> lvl;
        int start = (lvl == 0) ? 0 : ((lvl == 1) ? 25600 : 32000);
        float dim = (float)Wi;
        float2 rp = *(const float2*)(refp + ((size_t)(q0 + q) * NLEVELS + lvl) * 2);

        float px = (rp.x + off.x / dim) * dim - 0.5f;
        float py = (rp.y + off.y / dim) * dim - 0.5f;

        float x0f = floorf(px), y0f = floorf(py);
        int x0 = (int)x0f, y0 = (int)y0f;
        float wx1 = px - x0f, wy1 = py - y0f;
        float wx0 = 1.f - wx1, wy0 = 1.f - wy1;

        bool xok0 = (x0 >= 0)  && (x0 < Wi);
        bool xok1 = (x0 >= -1) && (x0 + 1 < Wi);

        const int hbase = h * VROWS;
        #pragma unroll
        for (int ytap = 0; ytap < 2; ytap++) {
            int y = y0 + ytap;
            bool yok = (y >= 0) && (y < Wi);
            float wy = ytap ? wy1 : wy0;
            float w0 = (yok && xok0) ? a * wy * wx0 : 0.f;
            float w1 = (yok && xok1) ? a * wy * wx1 : 0.f;
            int r = start + y * Wi + x0;
            int base;
            if (!yok) {
                base = 0; w0 = 0.f; w1 = 0.f;
            } else if (r < 0) {
                base = hbase * 64;          // rows (0,1): first half holds r+1 = 0
                w0 = w1; w1 = 0.f;
            } else if (r & 1) {
                base = COPYSZB + (hbase + (r - 1)) * 64;   // copy B, aligned
            } else {
                base = (hbase + r) * 64;                    // copy A, aligned
            }
            s_bo[q][p * 2 + ytap][h] = base;
            s_w[q][p * 2 + ytap][h][0] = w0;
            s_w[q][p * 2 + ytap][h][1] = w1;
        }
    }
    __syncthreads();

    // ---- stage 3: gather ----
    {
        const int wq   = tid >> 5;          // query within block
        const int lane = tid & 31;
        const int h0   = lane >> 3;         // head low bits (0-3)
        const int xh   = (lane >> 2) & 1;   // which 64B half (x-tap)
        const int b16  = lane & 7;          // 16B chunk within 128B
        const char* vbytes = (const char*)value;

        unsigned long long acc[2][4];
        #pragma unroll
        for (int gidx = 0; gidx < 2; gidx++)
            #pragma unroll
            for (int k = 0; k < 4; k++) acc[gidx][k] = 0;

        for (int pt = 0; pt < LP; pt++) {
            #pragma unroll
            for (int jj = 0; jj < 4; jj++) {
                const int ytap = jj >> 1, hgrp = jj & 1;
                const int head = hgrp * 4 + h0;
                const int idx = pt * 2 + ytap;
                int   bo = s_bo[wq][idx][head];
                float w  = s_w [wq][idx][head][xh];
                uint4 v = __ldg((const uint4*)(vbytes + bo + b16 * 16));
                unsigned long long wp2 = pack_f32x2(w, w);
                float2 f0 = __half22float2(*reinterpret_cast<__half2*>(&v.x));
                float2 f1 = __half22float2(*reinterpret_cast<__half2*>(&v.y));
                float2 f2 = __half22float2(*reinterpret_cast<__half2*>(&v.z));
                float2 f3 = __half22float2(*reinterpret_cast<__half2*>(&v.w));
                fma_f32x2(acc[hgrp][0], pack_f32x2(f0.x, f0.y), wp2);
                fma_f32x2(acc[hgrp][1], pack_f32x2(f1.x, f1.y), wp2);
                fma_f32x2(acc[hgrp][2], pack_f32x2(f2.x, f2.y), wp2);
                fma_f32x2(acc[hgrp][3], pack_f32x2(f3.x, f3.y), wp2);
            }
        }

        // combine x-halves (partner lane = lane ^ 4)
        #pragma unroll
        for (int gidx = 0; gidx < 2; gidx++)
            #pragma unroll
            for (int k = 0; k < 4; k++) {
                unsigned long long other =
                    __shfl_xor_sync(0xffffffffu, acc[gidx][k], 4);
                acc[gidx][k] = add_f32x2(acc[gidx][k], other);
            }

        if (xh == 0) {
            const int oct = lane & 3;
            #pragma unroll
            for (int gidx = 0; gidx < 2; gidx++) {
                const int head = gidx * 4 + h0;
                float f[8];
                unpack_f32x2(acc[gidx][0], f[0], f[1]);
                unpack_f32x2(acc[gidx][1], f[2], f[3]);
                unpack_f32x2(acc[gidx][2], f[4], f[5]);
                unpack_f32x2(acc[gidx][3], f[6], f[7]);
                __nv_bfloat16 hi[8], lo[8];
                #pragma unroll
                for (int k = 0; k < 8; k++) split_bf16(f[k], hi[k], lo[k]);
                uint4 HI = make_uint4(pack_bf2(hi[0],hi[1]), pack_bf2(hi[2],hi[3]),
                                      pack_bf2(hi[4],hi[5]), pack_bf2(hi[6],hi[7]));
                uint4 LO = make_uint4(pack_bf2(lo[0],lo[1]), pack_bf2(lo[2],lo[3]),
                                      pack_bf2(lo[4],lo[5]), pack_bf2(lo[6],lo[7]));
                size_t orow = (size_t)(q0 + wq) * KHL + head * HD + oct * 8;
                *(uint4*)(outb + orow)          = HI;
                *(uint4*)(outb + orow + DMODEL) = LO;
            }
        }
    }
}

// ---------------- launch ----------------
extern "C" void kernel_launch(void* const* d_in, const int* in_sizes, int n_in,
                              void* d_out, int out_size)
{
    const float* hidden = (const float*)d_in[0];
    const float* enc    = (const float*)d_in[1];
    const float* pos    = (const float*)d_in[2];
    const float* refp   = (const float*)d_in[3];
    const float* Wv     = (const float*)d_in[4];
    const float* bv     = (const float*)d_in[5];
    const float* Ws     = (const float*)d_in[6];
    const float* bs     = (const float*)d_in[7];
    const float* Wa     = (const float*)d_in[8];
    const float* ba     = (const float*)d_in[9];
    const float* Wo     = (const float*)d_in[10];
    const float* bo     = (const float*)d_in[11];

    float* out = (float*)d_out;
    float* attn_ptr = ((size_t)out_size >= OUT_ELEMS + ATTN_ELEMS) ? (out + OUT_ELEMS) : nullptr;

    __half* p_val2; float *p_raw, *p_b2;
    __nv_bfloat16 *p_encb, *p_hsb, *p_sampb, *p_wvb, *p_w2b, *p_wob;
    cudaGetSymbolAddress((void**)&p_val2,  g_val2);
    cudaGetSymbolAddress((void**)&p_raw,   g_raw);
    cudaGetSymbolAddress((void**)&p_b2,    g_b2);
    cudaGetSymbolAddress((void**)&p_encb,  g_encb);
    cudaGetSymbolAddress((void**)&p_hsb,   g_hsb);
    cudaGetSymbolAddress((void**)&p_sampb, g_sampb);
    cudaGetSymbolAddress((void**)&p_wvb,   g_wvb);
    cudaGetSymbolAddress((void**)&p_w2b,   g_w2b);
    cudaGetSymbolAddress((void**)&p_wob,   g_wob);

    static bool attr_set = false;
    if (!attr_set) {
        cudaFuncSetAttribute(gemm_kernel, cudaFuncAttributeMaxDynamicSharedMemorySize, 65536);
        attr_set = true;
    }

    // 1) weight prep + activation conversion
    prep_kernel<<<100, 256>>>(Wv, Ws, bs, Wa, ba, Wo);
    conv_act_kernel<<<(2 * SEQ * 32 + 255) / 256, 256>>>(enc, hidden, pos);

    const int grid_m = (SEQ + 127) / 128;   // 263

    // 2) fused: value(fp16, head-major dual copy) AND raw projections
    GemmJob jv = { p_encb, p_wvb, bv,   p_val2, DMODEL, 1 };
    GemmJob jr = { p_hsb,  p_w2b, p_b2, p_raw,  N2,     0 };
    {
        dim3 g(5, grid_m);
        gemm_kernel<<<g, 256, 65536>>>(jv, jr, 2, SEQ);
    }

    // 3) softmax + deformable sampling (emits bf16 hi|lo), 8 queries per block
    sample_kernel<<<SEQ / 8, 256>>>(p_val2, p_raw, refp, p_sampb, attn_ptr);

    // 4) output = samp @ Wo^T + bo
    GemmJob jo = { p_sampb, p_wob, bo, out, DMODEL, 0 };
    {
        dim3 g(2, grid_m);
        gemm_kernel<<<g, 256, 65536>>>(jo, jo, 2, SEQ);
    }
}

// round 10
// speedup vs baseline: 2.0370x; 1.1828x over previous
#include <cuda_runtime.h>
#include <cuda_bf16.h>
#include <cuda_fp16.h>
#include <math.h>
#include <stddef.h>
#include <stdint.h>

// ---------------- problem constants ----------------
#define SEQ      33600
#define DMODEL   256
#define NHEADS   8
#define NLEVELS  3
#define NPOINTS  4
#define LP       (NLEVELS * NPOINTS)        // 12
#define HD       (DMODEL / NHEADS)          // 32
#define NOFF     (NHEADS * LP * 2)          // 192
#define NATT     (NHEADS * LP)              // 96
#define N2       (NOFF + NATT)              // 288
#define KHL      512                         // weight hi|lo width
#define VROWS    (SEQ + 4)                   // padded rows per head
#define COPY_ELEMS ((size_t)NHEADS * VROWS * HD)
#define COPYSZB  ((int)(COPY_ELEMS * 2))
#define OUT_ELEMS  ((size_t)SEQ * DMODEL)
#define ATTN_ELEMS ((size_t)SEQ * NHEADS * LP)

// ---------------- scratch (device globals) ----------------
__device__ __half g_val2[2 * COPY_ELEMS];     // value, head-major, copies A|B(shifted)
__device__ float  g_raw [SEQ * N2];
__device__ float  g_b2  [N2];
__device__ __half g_ench [SEQ * DMODEL];      // enc        fp16
__device__ __half g_hsh  [SEQ * DMODEL];      // hidden+pos fp16
__device__ __half g_samph[SEQ * DMODEL];      // sampled    fp16
__device__ __half g_wvh[DMODEL * KHL];        // weights fp16 hi|lo
__device__ __half g_w2h[N2 * KHL];
__device__ __half g_woh[DMODEL * KHL];

// ---------------- helpers ----------------
__device__ __forceinline__ uint32_t pack_h2(__half a, __half b) {
    __half2 t = __halves2half2(a, b);
    return *reinterpret_cast<uint32_t*>(&t);
}
__device__ __forceinline__ void split_f16(float x, __half& h, __half& l) {
    h = __float2half_rn(x);
    l = __float2half_rn(x - __half2float(h));
}
// 8 floats -> fp16 hi 16B + lo 16B
__device__ __forceinline__ void cvt8_hilo(float4 a, float4 b, uint4& H, uint4& L) {
    __half h[8], l[8];
    split_f16(a.x, h[0], l[0]); split_f16(a.y, h[1], l[1]);
    split_f16(a.z, h[2], l[2]); split_f16(a.w, h[3], l[3]);
    split_f16(b.x, h[4], l[4]); split_f16(b.y, h[5], l[5]);
    split_f16(b.z, h[6], l[6]); split_f16(b.w, h[7], l[7]);
    H = make_uint4(pack_h2(h[0],h[1]), pack_h2(h[2],h[3]), pack_h2(h[4],h[5]), pack_h2(h[6],h[7]));
    L = make_uint4(pack_h2(l[0],l[1]), pack_h2(l[2],l[3]), pack_h2(l[4],l[5]), pack_h2(l[6],l[7]));
}
// 8 floats -> fp16 16B
__device__ __forceinline__ uint4 cvt8_f16(float4 a, float4 b) {
    __half2 p0 = __floats2half2_rn(a.x, a.y);
    __half2 p1 = __floats2half2_rn(a.z, a.w);
    __half2 p2 = __floats2half2_rn(b.x, b.y);
    __half2 p3 = __floats2half2_rn(b.z, b.w);
    return make_uint4(*(uint32_t*)&p0, *(uint32_t*)&p1, *(uint32_t*)&p2, *(uint32_t*)&p3);
}
__device__ __forceinline__ void cp_async16(uint32_t dst, const void* src, bool pred) {
    int sz = pred ? 16 : 0;
    asm volatile("cp.async.cg.shared.global [%0], [%1], 16, %2;"
                 :: "r"(dst), "l"(src), "r"(sz) : "memory");
}
// packed f32x2 helpers (sm_100+ base feature)
__device__ __forceinline__ unsigned long long pack_f32x2(float lo, float hi) {
    unsigned long long r;
    asm("mov.b64 %0, {%1, %2};" : "=l"(r) : "f"(lo), "f"(hi));
    return r;
}
__device__ __forceinline__ void unpack_f32x2(unsigned long long v, float& lo, float& hi) {
    asm("mov.b64 {%0, %1}, %2;" : "=f"(lo), "=f"(hi) : "l"(v));
}
__device__ __forceinline__ void fma_f32x2(unsigned long long& d,
                                          unsigned long long a, unsigned long long b) {
    asm("fma.rn.f32x2 %0, %1, %2, %0;" : "+l"(d) : "l"(a), "l"(b));
}
__device__ __forceinline__ unsigned long long add_f32x2(unsigned long long a, unsigned long long b) {
    unsigned long long r;
    asm("add.rn.f32x2 %0, %1, %2;" : "=l"(r) : "l"(a), "l"(b));
    return r;
}

// ---------------- weight prep: fp32 -> fp16 hi|lo + b2 ----------------
__global__ __launch_bounds__(256) void prep_kernel(
    const float* __restrict__ Wv, const float* __restrict__ Ws, const float* __restrict__ bs,
    const float* __restrict__ Wa, const float* __restrict__ ba, const float* __restrict__ Wo)
{
    int u = blockIdx.x * 256 + threadIdx.x;     // one unit = 8 floats
    const int TOTAL_ROWS = DMODEL + N2 + DMODEL;  // 800
    if (u < TOTAL_ROWS * 32) {
        int row = u >> 5, uc = u & 31;
        const float* src;
        __half* dst;
        if (row < DMODEL) { src = Wv + (size_t)row * DMODEL; dst = g_wvh + (size_t)row * KHL; }
        else if (row < DMODEL + N2) {
            int n = row - DMODEL;
            src = (n < NOFF) ? (Ws + (size_t)n * DMODEL) : (Wa + (size_t)(n - NOFF) * DMODEL);
            dst = g_w2h + (size_t)n * KHL;
        } else {
            int n = row - DMODEL - N2;
            src = Wo + (size_t)n * DMODEL; dst = g_woh + (size_t)n * KHL;
        }
        float4 a = *(const float4*)(src + uc * 8);
        float4 b = *(const float4*)(src + uc * 8 + 4);
        uint4 H, L; cvt8_hilo(a, b, H, L);
        *(uint4*)(dst + uc * 8)          = H;
        *(uint4*)(dst + DMODEL + uc * 8) = L;
    }
    if (u < N2) g_b2[u] = (u < NOFF) ? bs[u] : ba[u - NOFF];
}

// ---------------- activation conversion: enc and hidden+pos -> fp16 ----------------
__global__ __launch_bounds__(256) void conv_act_kernel(
    const float* __restrict__ enc, const float* __restrict__ hidden, const float* __restrict__ pos)
{
    int u = blockIdx.x * 256 + threadIdx.x;
    const int PER = SEQ * 32;                 // units per tensor (8 floats each)
    if (u >= 2 * PER) return;
    bool second = (u >= PER);
    int v = second ? (u - PER) : u;
    int row = v >> 5, uc = v & 31;
    const float* src = (second ? hidden : enc) + (size_t)row * DMODEL + uc * 8;
    float4 a = *(const float4*)(src);
    float4 b = *(const float4*)(src + 4);
    if (second) {
        const float* p2 = pos + (size_t)row * DMODEL + uc * 8;
        float4 u0 = *(const float4*)p2, u1 = *(const float4*)(p2 + 4);
        a.x += u0.x; a.y += u0.y; a.z += u0.z; a.w += u0.w;
        b.x += u1.x; b.y += u1.y; b.z += u1.z; b.w += u1.w;
    }
    __half* dst = (second ? g_hsh : g_ench) + (size_t)row * DMODEL;
    *(uint4*)(dst + uc * 8) = cvt8_f16(a, b);
}

// ---------------- GEMM: C[M,N] = A @ Bw^T + bias (fp16 A, fp16 hi/lo B, 2 passes) ----------------
// A: fp16 [M,256]; Bw: fp16 [N,512]=[hi|lo]. 8 K-chunks of 64:
// chunks 0-3: A*Bh, 4-7: A*Bl. fp32 accum.
struct GemmJob {
    const __half* A;
    const __half* Bw;
    const float* bias;
    void* C;
    int N;
    int out_half;   // 1: write __half head-major dual-copy (value), 0: write float
};

__global__ __launch_bounds__(256, 2) void gemm_kernel(GemmJob j0, GemmJob j1, int xsplit, int M)
{
    extern __shared__ char smem[];   // 2 x (16KB A + 16KB B) = 64 KB

    const bool first = ((int)blockIdx.x < xsplit);
    GemmJob j = first ? j0 : j1;
    const int nb = first ? blockIdx.x : (blockIdx.x - xsplit);
    const int blk_m = blockIdx.y * 128, blk_n = nb * 128;

    const int tid = threadIdx.x;
    const int wid = tid >> 5, lane = tid & 31;
    const int warp_m = wid & 3, warp_n = wid >> 2;
    const int t4 = lane >> 3, r8 = lane & 7;

    const uint32_t s_base = (uint32_t)__cvta_generic_to_shared(smem);

    int lrow[4], luc[4];
    uint32_t s_off[4];
    bool predA[4], predB[4];
    const __half* srcA[4];
    const __half* srcB[4];
    #pragma unroll
    for (int i = 0; i < 4; i++) {
        int u = tid + 256 * i;
        lrow[i] = u >> 3; luc[i] = u & 7;
        s_off[i] = (uint32_t)(lrow[i] * 128 + ((luc[i] ^ (lrow[i] & 7)) << 4));
        int gm = blk_m + lrow[i];
        predA[i] = gm < M;
        srcA[i] = j.A + (size_t)(predA[i] ? gm : 0) * DMODEL + luc[i] * 8;
        int gn = blk_n + lrow[i];
        predB[i] = gn < j.N;
        srcB[i] = j.Bw + (size_t)(predB[i] ? gn : 0) * KHL + luc[i] * 8;
    }

    float acc[2][8][4];
    #pragma unroll
    for (int a = 0; a < 2; a++)
        #pragma unroll
        for (int b = 0; b < 8; b++)
            #pragma unroll
            for (int c = 0; c < 4; c++) acc[a][b][c] = 0.f;

    auto issue = [&](int c, int buf) {
        int pass = c >> 2, kk = (c & 3) * 64;
        int bcol = pass * DMODEL + kk;
        uint32_t abase = s_base + buf * 32768;
        uint32_t bbase = abase + 16384;
        #pragma unroll
        for (int i = 0; i < 4; i++) {
            cp_async16(abase + s_off[i], srcA[i] + kk,   predA[i]);
            cp_async16(bbase + s_off[i], srcB[i] + bcol, predB[i]);
        }
        asm volatile("cp.async.commit_group;" ::: "memory");
    };

    issue(0, 0);

    for (int c = 0; c < 8; c++) {
        if (c + 1 < 8) {
            issue(c + 1, (c + 1) & 1);
            asm volatile("cp.async.wait_group 1;" ::: "memory");
        } else {
            asm volatile("cp.async.wait_group 0;" ::: "memory");
        }
        __syncthreads();

        const uint32_t abase = s_base + (c & 1) * 32768;
        const uint32_t bbase = abase + 16384;

        #pragma unroll
        for (int ks = 0; ks < 4; ks++) {
            uint32_t af[2][4];
            #pragma unroll
            for (int mi = 0; mi < 2; mi++) {
                int row = warp_m * 32 + mi * 16 + (t4 & 1) * 8 + r8;
                int kch = ks * 2 + (t4 >> 1);
                uint32_t addr = abase + (uint32_t)(row * 128 + ((kch ^ (row & 7)) << 4));
                asm volatile("ldmatrix.sync.aligned.m8n8.x4.shared.b16 {%0,%1,%2,%3}, [%4];"
                             : "=r"(af[mi][0]), "=r"(af[mi][1]), "=r"(af[mi][2]), "=r"(af[mi][3])
                             : "r"(addr));
            }
            uint32_t bf[4][4];
            #pragma unroll
            for (int jj = 0; jj < 4; jj++) {
                int nrow = warp_n * 64 + jj * 16 + (t4 >> 1) * 8 + r8;
                int kch = ks * 2 + (t4 & 1);
                uint32_t addr = bbase + (uint32_t)(nrow * 128 + ((kch ^ (nrow & 7)) << 4));
                asm volatile("ldmatrix.sync.aligned.m8n8.x4.shared.b16 {%0,%1,%2,%3}, [%4];"
                             : "=r"(bf[jj][0]), "=r"(bf[jj][1]), "=r"(bf[jj][2]), "=r"(bf[jj][3])
                             : "r"(addr));
            }
            #pragma unroll
            for (int mi = 0; mi < 2; mi++)
                #pragma unroll
                for (int nj = 0; nj < 8; nj++) {
                    uint32_t b0 = bf[nj >> 1][(nj & 1) * 2 + 0];
                    uint32_t b1 = bf[nj >> 1][(nj & 1) * 2 + 1];
                    asm volatile(
                        "mma.sync.aligned.m16n8k16.row.col.f32.f16.f16.f32 "
                        "{%0,%1,%2,%3}, {%4,%5,%6,%7}, {%8,%9}, {%0,%1,%2,%3};"
                        : "+f"(acc[mi][nj][0]), "+f"(acc[mi][nj][1]),
                          "+f"(acc[mi][nj][2]), "+f"(acc[mi][nj][3])
                        : "r"(af[mi][0]), "r"(af[mi][1]), "r"(af[mi][2]), "r"(af[mi][3]),
                          "r"(b0), "r"(b1));
                }
        }
        __syncthreads();
    }

    // epilogue
    const int g = lane >> 2, tg = lane & 3;
    #pragma unroll
    for (int mi = 0; mi < 2; mi++) {
        int row0 = blk_m + warp_m * 32 + mi * 16 + g;
        #pragma unroll
        for (int nj = 0; nj < 8; nj++) {
            int col = blk_n + warp_n * 64 + nj * 8 + tg * 2;
            if (col >= j.N) continue;
            float b0 = __ldg(j.bias + col), b1 = __ldg(j.bias + col + 1);
            if (j.out_half) {
                // head-major dual-copy value store
                __half* C = (__half*)j.C;
                int h = col >> 5, ch = col & 31;
                #pragma unroll
                for (int rr = 0; rr < 2; rr++) {
                    int row = row0 + rr * 8;
                    if (row >= M) continue;
                    __half2 o = __floats2half2_rn(acc[mi][nj][rr * 2 + 0] + b0,
                                                  acc[mi][nj][rr * 2 + 1] + b1);
                    size_t eA = ((size_t)h * VROWS + row) * HD + ch;
                    *(__half2*)(C + eA) = o;
                    int slotB = (row == 0) ? (SEQ + 2) : (row - 1);
                    *(__half2*)(C + COPY_ELEMS + ((size_t)h * VROWS + slotB) * HD + ch) = o;
                }
            } else {
                float* C = (float*)j.C;
                if (row0 < M) {
                    float2 o = make_float2(acc[mi][nj][0] + b0, acc[mi][nj][1] + b1);
                    *(float2*)(C + (size_t)row0 * j.N + col) = o;
                }
                if (row0 + 8 < M) {
                    float2 o = make_float2(acc[mi][nj][2] + b0, acc[mi][nj][3] + b1);
                    *(float2*)(C + (size_t)(row0 + 8) * j.N + col) = o;
                }
            }
        }
    }
}

// ---------------- sampling: 8 queries/block, warp=query, pair-aligned gather ----------------
__global__ __launch_bounds__(256) void sample_kernel(
    const __half* __restrict__ value,      // g_val2
    const float* __restrict__ raw,         // [SEQ, 288]
    const float* __restrict__ refp,        // [SEQ, 3, 2]
    __half* __restrict__ outh,             // [SEQ, 256] fp16
    float* __restrict__ attn_out)          // [SEQ, 8, 12] or null
{
    const int q0  = blockIdx.x * 8;
    const int tid = threadIdx.x;

    __shared__ float s_attn[64][LP];            // [q*8+h][p]
    __shared__ int   s_bo[8][24][NHEADS];       // [q][p*2+ytap][h] byte offset
    __shared__ float s_w [8][24][NHEADS][2];    // weights for the two 64B halves

    // ---- stage 1: softmax ----
    if (tid < 64) {
        int q = tid >> 3, h = tid & 7;
        const float* lg = raw + (size_t)(q0 + q) * N2 + NOFF + h * LP;
        float l[LP]; float m = -INFINITY;
        #pragma unroll
        for (int p = 0; p < LP; p++) { l[p] = lg[p]; m = fmaxf(m, l[p]); }
        float s = 0.f;
        #pragma unroll
        for (int p = 0; p < LP; p++) { l[p] = expf(l[p] - m); s += l[p]; }
        float inv = 1.f / s;
        #pragma unroll
        for (int p = 0; p < LP; p++) s_attn[q * 8 + h][p] = l[p] * inv;
    }
    __syncthreads();

    // ---- stage 2: tap setup (768 slots, 3 per thread) ----
    #pragma unroll
    for (int i = 0; i < 3; i++) {
        int s = i * 256 + tid;
        int q = s / 96; int rem = s - q * 96;
        int h = rem / LP; int p = rem - h * LP;

        float a = s_attn[q * 8 + h][p];
        if (attn_out) attn_out[((size_t)(q0 + q) * NHEADS + h) * LP + p] = a;

        const float* rq = raw + (size_t)(q0 + q) * N2;
        float2 off = *(const float2*)(rq + (h * LP + p) * 2);
        int lvl = p >> 2;
        int Wi = 160 >> lvl;
        int start = (lvl == 0) ? 0 : ((lvl == 1) ? 25600 : 32000);
        float dim = (float)Wi;
        float2 rp = *(const float2*)(refp + ((size_t)(q0 + q) * NLEVELS + lvl) * 2);

        float px = (rp.x + off.x / dim) * dim - 0.5f;
        float py = (rp.y + off.y / dim) * dim - 0.5f;

        float x0f = floorf(px), y0f = floorf(py);
        int x0 = (int)x0f, y0 = (int)y0f;
        float wx1 = px - x0f, wy1 = py - y0f;
        float wx0 = 1.f - wx1, wy0 = 1.f - wy1;

        bool xok0 = (x0 >= 0)  && (x0 < Wi);
        bool xok1 = (x0 >= -1) && (x0 + 1 < Wi);

        const int hbase = h * VROWS;
        #pragma unroll
        for (int ytap = 0; ytap < 2; ytap++) {
            int y = y0 + ytap;
            bool yok = (y >= 0) && (y < Wi);
            float wy = ytap ? wy1 : wy0;
            float w0 = (yok && xok0) ? a * wy * wx0 : 0.f;
            float w1 = (yok && xok1) ? a * wy * wx1 : 0.f;
            int r = start + y * Wi + x0;
            int base;
            if (!yok) {
                base = 0; w0 = 0.f; w1 = 0.f;
            } else if (r < 0) {
                base = hbase * 64;          // rows (0,1): first half holds r+1 = 0
                w0 = w1; w1 = 0.f;
            } else if (r & 1) {
                base = COPYSZB + (hbase + (r - 1)) * 64;   // copy B, aligned
            } else {
                base = (hbase + r) * 64;                    // copy A, aligned
            }
            s_bo[q][p * 2 + ytap][h] = base;
            s_w[q][p * 2 + ytap][h][0] = w0;
            s_w[q][p * 2 + ytap][h][1] = w1;
        }
    }
    __syncthreads();

    // ---- stage 3: gather ----
    {
        const int wq   = tid >> 5;          // query within block
        const int lane = tid & 31;
        const int h0   = lane >> 3;         // head low bits (0-3)
        const int xh   = (lane >> 2) & 1;   // which 64B half (x-tap)
        const int b16  = lane & 7;          // 16B chunk within 128B
        const char* vbytes = (const char*)value;

        unsigned long long acc[2][4];
        #pragma unroll
        for (int gidx = 0; gidx < 2; gidx++)
            #pragma unroll
            for (int k = 0; k < 4; k++) acc[gidx][k] = 0;

        for (int pt = 0; pt < LP; pt++) {
            #pragma unroll
            for (int jj = 0; jj < 4; jj++) {
                const int ytap = jj >> 1, hgrp = jj & 1;
                const int head = hgrp * 4 + h0;
                const int idx = pt * 2 + ytap;
                int   bo = s_bo[wq][idx][head];
                float w  = s_w [wq][idx][head][xh];
                uint4 v = __ldg((const uint4*)(vbytes + bo + b16 * 16));
                unsigned long long wp2 = pack_f32x2(w, w);
                float2 f0 = __half22float2(*reinterpret_cast<__half2*>(&v.x));
                float2 f1 = __half22float2(*reinterpret_cast<__half2*>(&v.y));
                float2 f2 = __half22float2(*reinterpret_cast<__half2*>(&v.z));
                float2 f3 = __half22float2(*reinterpret_cast<__half2*>(&v.w));
                fma_f32x2(acc[hgrp][0], pack_f32x2(f0.x, f0.y), wp2);
                fma_f32x2(acc[hgrp][1], pack_f32x2(f1.x, f1.y), wp2);
                fma_f32x2(acc[hgrp][2], pack_f32x2(f2.x, f2.y), wp2);
                fma_f32x2(acc[hgrp][3], pack_f32x2(f3.x, f3.y), wp2);
            }
        }

        // combine x-halves (partner lane = lane ^ 4)
        #pragma unroll
        for (int gidx = 0; gidx < 2; gidx++)
            #pragma unroll
            for (int k = 0; k < 4; k++) {
                unsigned long long other =
                    __shfl_xor_sync(0xffffffffu, acc[gidx][k], 4);
                acc[gidx][k] = add_f32x2(acc[gidx][k], other);
            }

        if (xh == 0) {
            const int oct = lane & 3;
            #pragma unroll
            for (int gidx = 0; gidx < 2; gidx++) {
                const int head = gidx * 4 + h0;
                float f[8];
                unpack_f32x2(acc[gidx][0], f[0], f[1]);
                unpack_f32x2(acc[gidx][1], f[2], f[3]);
                unpack_f32x2(acc[gidx][2], f[4], f[5]);
                unpack_f32x2(acc[gidx][3], f[6], f[7]);
                uint4 O = cvt8_f16(make_float4(f[0], f[1], f[2], f[3]),
                                   make_float4(f[4], f[5], f[6], f[7]));
                size_t orow = (size_t)(q0 + wq) * DMODEL + head * HD + oct * 8;
                *(uint4*)(outh + orow) = O;
            }
        }
    }
}

// ---------------- launch ----------------
extern "C" void kernel_launch(void* const* d_in, const int* in_sizes, int n_in,
                              void* d_out, int out_size)
{
    const float* hidden = (const float*)d_in[0];
    const float* enc    = (const float*)d_in[1];
    const float* pos    = (const float*)d_in[2];
    const float* refp   = (const float*)d_in[3];
    const float* Wv     = (const float*)d_in[4];
    const float* bv     = (const float*)d_in[5];
    const float* Ws     = (const float*)d_in[6];
    const float* bs     = (const float*)d_in[7];
    const float* Wa     = (const float*)d_in[8];
    const float* ba     = (const float*)d_in[9];
    const float* Wo     = (const float*)d_in[10];
    const float* bo     = (const float*)d_in[11];

    float* out = (float*)d_out;
    float* attn_ptr = ((size_t)out_size >= OUT_ELEMS + ATTN_ELEMS) ? (out + OUT_ELEMS) : nullptr;

    __half *p_val2, *p_ench, *p_hsh, *p_samph, *p_wvh, *p_w2h, *p_woh;
    float *p_raw, *p_b2;
    cudaGetSymbolAddress((void**)&p_val2,  g_val2);
    cudaGetSymbolAddress((void**)&p_raw,   g_raw);
    cudaGetSymbolAddress((void**)&p_b2,    g_b2);
    cudaGetSymbolAddress((void**)&p_ench,  g_ench);
    cudaGetSymbolAddress((void**)&p_hsh,   g_hsh);
    cudaGetSymbolAddress((void**)&p_samph, g_samph);
    cudaGetSymbolAddress((void**)&p_wvh,   g_wvh);
    cudaGetSymbolAddress((void**)&p_w2h,   g_w2h);
    cudaGetSymbolAddress((void**)&p_woh,   g_woh);

    static bool attr_set = false;
    if (!attr_set) {
        cudaFuncSetAttribute(gemm_kernel, cudaFuncAttributeMaxDynamicSharedMemorySize, 65536);
        attr_set = true;
    }

    // 1) weight prep + activation conversion
    prep_kernel<<<100, 256>>>(Wv, Ws, bs, Wa, ba, Wo);
    conv_act_kernel<<<(2 * SEQ * 32 + 255) / 256, 256>>>(enc, hidden, pos);

    const int grid_m = (SEQ + 127) / 128;   // 263

    // 2) fused: value(fp16, head-major dual copy) AND raw projections
    GemmJob jv = { p_ench, p_wvh, bv,   p_val2, DMODEL, 1 };
    GemmJob jr = { p_hsh,  p_w2h, p_b2, p_raw,  N2,     0 };
    {
        dim3 g(5, grid_m);
        gemm_kernel<<<g, 256, 65536>>>(jv, jr, 2, SEQ);
    }

    // 3) softmax + deformable sampling (emits fp16), 8 queries per block
    sample_kernel<<<SEQ / 8, 256>>>(p_val2, p_raw, refp, p_samph, attn_ptr);

    // 4) output = samp @ Wo^T + bo
    GemmJob jo = { p_samph, p_woh, bo, out, DMODEL, 0 };
    {
        dim3 g(2, grid_m);
        gemm_kernel<<<g, 256, 65536>>>(jo, jo, 2, SEQ);
    }
}